// round 1
// baseline (speedup 1.0000x reference)
#include <cuda_runtime.h>
#include <math.h>
#include <float.h>

#define BATCH 2
#define SEQ 2048
#define DMODEL 2048
#define NH 16
#define HD 128
#define ROT 64
#define RHALF 32
#define NMEM 16
#define JTOT (SEQ + NMEM)   // 2064
#define QKSCALE 10.0f

// ---------------- scratch (device globals; no allocations allowed) ----------
__device__ float g_q[BATCH * NH * SEQ * HD];          // (b,h,n,d)
__device__ float g_k[BATCH * NH * JTOT * HD];         // (b,h,j,d), rows [0,16) = memory
__device__ float g_v[BATCH * NH * JTOT * HD];         // (b,h,j,d)
__device__ float g_gate[BATCH * SEQ * DMODEL];        // x@Wg + bg
__device__ float g_simA[BATCH * NH * SEQ * JTOT];     // 541 MB
__device__ float g_simB[BATCH * NH * SEQ * JTOT];     // 541 MB
__device__ float g_ao[BATCH * SEQ * DMODEL];          // gated attention output (b,n,h*d)

// ---------------- generic 128x128x8 SGEMM: C(4096x2048) = A(4096x2048) @ W(2048x2048)
// mode 0: scatter to (b,h,n,d)  [Q]
// mode 1: scatter to (b,h,NMEM+n,d)  [K,V]
// mode 2: plain row-major + optional bias  [gate, final]
__global__ __launch_bounds__(256) void sgemm_k(const float* __restrict__ A,
                                               const float* __restrict__ W,
                                               const float* __restrict__ bias,
                                               float* __restrict__ C, int mode)
{
    __shared__ float As[8][128];
    __shared__ float Bs[8][132];

    const int tx = threadIdx.x;
    const int trow = tx >> 4;          // 0..15
    const int tcol = tx & 15;          // 0..15
    const int rowBase = blockIdx.y * 128;
    const int colBase = blockIdx.x * 128;

    float acc[8][8];
#pragma unroll
    for (int i = 0; i < 8; i++)
#pragma unroll
        for (int j = 0; j < 8; j++) acc[i][j] = 0.f;

    const int ar = tx >> 1, ak = (tx & 1) << 2;    // A: 128 rows x 8 k
    const int br = tx >> 5, bc = (tx & 31) << 2;   // W: 8 k x 128 cols

    for (int k0 = 0; k0 < DMODEL; k0 += 8) {
        float4 av = *(const float4*)(A + (size_t)(rowBase + ar) * DMODEL + k0 + ak);
        As[ak + 0][ar] = av.x; As[ak + 1][ar] = av.y;
        As[ak + 2][ar] = av.z; As[ak + 3][ar] = av.w;
        float4 wv = *(const float4*)(W + (size_t)(k0 + br) * DMODEL + colBase + bc);
        *(float4*)(&Bs[br][bc]) = wv;
        __syncthreads();
#pragma unroll
        for (int kk = 0; kk < 8; kk++) {
            float a[8], b[8];
#pragma unroll
            for (int i = 0; i < 8; i++) a[i] = As[kk][trow * 8 + i];
#pragma unroll
            for (int j = 0; j < 8; j++) b[j] = Bs[kk][tcol * 8 + j];
#pragma unroll
            for (int i = 0; i < 8; i++)
#pragma unroll
                for (int j = 0; j < 8; j++) acc[i][j] = fmaf(a[i], b[j], acc[i][j]);
        }
        __syncthreads();
    }

#pragma unroll
    for (int i = 0; i < 8; i++) {
        const int m = rowBase + trow * 8 + i;
        const int bb = m / SEQ, si = m % SEQ;
#pragma unroll
        for (int j = 0; j < 8; j++) {
            const int c = colBase + tcol * 8 + j;
            float v = acc[i][j];
            if (mode == 2) {
                if (bias) v += bias[c];
                C[(size_t)m * DMODEL + c] = v;
            } else {
                const int h = c >> 7, dd = c & 127;
                if (mode == 0)
                    C[(((size_t)(bb * NH + h)) * SEQ + si) * HD + dd] = v;
                else
                    C[(((size_t)(bb * NH + h)) * JTOT + NMEM + si) * HD + dd] = v;
            }
        }
    }
}

// ---------------- memory K/V prefix: mk = l2norm(mem_k)*k_scale; mv = mem_v ----
__global__ void mem_prefix_k(const float* __restrict__ mem_k,
                             const float* __restrict__ mem_v,
                             const float* __restrict__ k_scale)
{
    const int idx = blockIdx.x;             // h*NMEM + jm
    const int h = idx / NMEM, jm = idx % NMEM;
    const int t = threadIdx.x;              // 0..127
    float kv = mem_k[(size_t)idx * HD + t];
    float ss = kv * kv;
    __shared__ float red[4];
    for (int o = 16; o; o >>= 1) ss += __shfl_down_sync(0xffffffffu, ss, o);
    if ((t & 31) == 0) red[t >> 5] = ss;
    __syncthreads();
    const float tot = red[0] + red[1] + red[2] + red[3];
    const float inv = 1.f / fmaxf(sqrtf(tot), 1e-12f);
    const float mk = kv * inv * k_scale[t];
    const float mv = mem_v[(size_t)idx * HD + t];
    for (int b = 0; b < BATCH; b++) {
        const size_t off = (((size_t)(b * NH + h)) * JTOT + jm) * HD + t;
        g_k[off] = mk;
        g_v[off] = mv;
    }
}

// ---------------- per-row l2norm*scale (optional) + RoPE on first 64 dims -----
__global__ void norm_rope_k(float* __restrict__ buf, int rowStride, int rowOff,
                            const float* __restrict__ scale,
                            const float* __restrict__ freqs, int doNorm)
{
    const int idx = blockIdx.x;                  // bh*SEQ + i
    const int i = idx % SEQ;
    const int bh = idx / SEQ;
    float* row = buf + ((size_t)bh * rowStride + rowOff + i) * HD;
    const int t = threadIdx.x;                   // 0..127
    float v = row[t];
    __shared__ float red[4];
    __shared__ float sh[HD];
    if (doNorm) {
        float ss = v * v;
        for (int o = 16; o; o >>= 1) ss += __shfl_down_sync(0xffffffffu, ss, o);
        if ((t & 31) == 0) red[t >> 5] = ss;
        __syncthreads();
        const float tot = red[0] + red[1] + red[2] + red[3];
        const float inv = 1.f / fmaxf(sqrtf(tot), 1e-12f);
        v = v * inv * scale[t];
    }
    sh[t] = v;
    __syncthreads();
    float outv = v;
    if (t < ROT) {
        const float f = freqs[(size_t)i * ROT + t];
        const float c = cosf(f), s = sinf(f);
        const float rot = (t < RHALF) ? -sh[t + RHALF] : sh[t - RHALF];
        outv = v * c + rot * s;
    }
    row[t] = outv;
}

// ---------------- batched QK^T: simA[b,h,i,jj] = 10 * q.k -----------------------
__global__ __launch_bounds__(256) void qk_gemm_k()
{
    __shared__ float Qs[16][64];
    __shared__ float Ks[16][64];
    const int bh = blockIdx.z;
    const size_t qbase = (size_t)bh * SEQ * HD;
    const size_t kbase = (size_t)bh * JTOT * HD;
    const size_t sbase = (size_t)bh * SEQ * JTOT;
    const int i0 = blockIdx.y * 64;
    const int jj0 = blockIdx.x * 64;
    const int tx = threadIdx.x;
    const int trow = tx >> 4, tcol = tx & 15;
    const int lr = tx >> 2, lc = (tx & 3) << 2;

    float acc[4][4];
#pragma unroll
    for (int i = 0; i < 4; i++)
#pragma unroll
        for (int j = 0; j < 4; j++) acc[i][j] = 0.f;

    for (int k0 = 0; k0 < HD; k0 += 16) {
        float4 qv = *(const float4*)(g_q + qbase + (size_t)(i0 + lr) * HD + k0 + lc);
        Qs[lc + 0][lr] = qv.x; Qs[lc + 1][lr] = qv.y;
        Qs[lc + 2][lr] = qv.z; Qs[lc + 3][lr] = qv.w;
        const int jr = jj0 + lr;
        float4 kv = make_float4(0.f, 0.f, 0.f, 0.f);
        if (jr < JTOT)
            kv = *(const float4*)(g_k + kbase + (size_t)jr * HD + k0 + lc);
        Ks[lc + 0][lr] = kv.x; Ks[lc + 1][lr] = kv.y;
        Ks[lc + 2][lr] = kv.z; Ks[lc + 3][lr] = kv.w;
        __syncthreads();
#pragma unroll
        for (int kk = 0; kk < 16; kk++) {
            float a[4], b[4];
#pragma unroll
            for (int i = 0; i < 4; i++) a[i] = Qs[kk][trow * 4 + i];
#pragma unroll
            for (int j = 0; j < 4; j++) b[j] = Ks[kk][tcol * 4 + j];
#pragma unroll
            for (int i = 0; i < 4; i++)
#pragma unroll
                for (int j = 0; j < 4; j++) acc[i][j] = fmaf(a[i], b[j], acc[i][j]);
        }
        __syncthreads();
    }
#pragma unroll
    for (int i = 0; i < 4; i++) {
        const int ii = i0 + trow * 4 + i;
#pragma unroll
        for (int j = 0; j < 4; j++) {
            const int jj = jj0 + tcol * 4 + j;
            if (jj < JTOT)
                g_simA[sbase + (size_t)ii * JTOT + jj] = acc[i][j] * QKSCALE;
        }
    }
}

// ---------------- talking-heads mix across h (+ causal/memory mask on pre) -----
__global__ void talk_k(const float* __restrict__ src, float* __restrict__ dst,
                       const float* __restrict__ T, int doMask)
{
    __shared__ float Tm[NH * NH];
    const int t = threadIdx.x;
    if (t < NH * NH) Tm[t] = T[t];
    __syncthreads();
    const int jj = blockIdx.x * 256 + t;
    const int i = blockIdx.y, b = blockIdx.z;
    if (jj >= JTOT) return;
    const size_t base = (((size_t)b * NH) * SEQ + i) * JTOT + jj;
    const size_t hstride = (size_t)SEQ * JTOT;
    if (doMask && jj > i + NMEM) {
#pragma unroll
        for (int g = 0; g < NH; g++) dst[base + (size_t)g * hstride] = -FLT_MAX;
        return;
    }
    float s[NH];
#pragma unroll
    for (int h = 0; h < NH; h++) s[h] = src[base + (size_t)h * hstride];
#pragma unroll
    for (int g = 0; g < NH; g++) {
        float o = 0.f;
#pragma unroll
        for (int h = 0; h < NH; h++) o = fmaf(Tm[g * NH + h], s[h], o);
        dst[base + (size_t)g * hstride] = o;
    }
}

// ---------------- row softmax over jj (in place) --------------------------------
__global__ void softmax_k(float* __restrict__ buf)
{
    const int idx = blockIdx.x;                  // (b*h)*SEQ + i
    float* row = buf + (size_t)idx * JTOT;
    const int t = threadIdx.x;                   // 0..255
    float loc[9];
    float m = -FLT_MAX;
#pragma unroll
    for (int c = 0; c < 9; c++) {
        const int jj = t + c * 256;
        if (jj < JTOT) { const float v = row[jj]; loc[c] = v; m = fmaxf(m, v); }
        else loc[c] = -FLT_MAX;
    }
    __shared__ float red[8];
    for (int o = 16; o; o >>= 1) m = fmaxf(m, __shfl_xor_sync(0xffffffffu, m, o));
    if ((t & 31) == 0) red[t >> 5] = m;
    __syncthreads();
    m = red[0];
#pragma unroll
    for (int w = 1; w < 8; w++) m = fmaxf(m, red[w]);
    __syncthreads();
    float sum = 0.f;
#pragma unroll
    for (int c = 0; c < 9; c++) {
        const int jj = t + c * 256;
        if (jj < JTOT) { const float e = __expf(loc[c] - m); loc[c] = e; sum += e; }
    }
    for (int o = 16; o; o >>= 1) sum += __shfl_xor_sync(0xffffffffu, sum, o);
    if ((t & 31) == 0) red[t >> 5] = sum;
    __syncthreads();
    float tot = 0.f;
#pragma unroll
    for (int w = 0; w < 8; w++) tot += red[w];
    const float inv = 1.f / tot;
#pragma unroll
    for (int c = 0; c < 9; c++) {
        const int jj = t + c * 256;
        if (jj < JTOT) row[jj] = loc[c] * inv;
    }
}

// ---------------- PV GEMM + head_scale + sigmoid gating -------------------------
__global__ __launch_bounds__(256) void av_gemm_k(const float* __restrict__ hs_params)
{
    __shared__ float Ps[16][64];
    __shared__ float Vs[16][128];
    const int bg = blockIdx.z;
    const int b = bg / NH, g = bg % NH;
    const size_t pbase = (size_t)bg * SEQ * JTOT;
    const size_t vbase = (size_t)bg * JTOT * HD;
    const int i0 = blockIdx.y * 64;
    const int tx = threadIdx.x;
    const int trow = tx >> 4, tcol = tx & 15;
    const int pr = tx >> 2, pc = (tx & 3) << 2;
    const int vr = tx >> 4, vc = (tx & 15) << 3;

    float acc[4][8];
#pragma unroll
    for (int i = 0; i < 4; i++)
#pragma unroll
        for (int j = 0; j < 8; j++) acc[i][j] = 0.f;

    for (int k0 = 0; k0 < JTOT; k0 += 16) {
        float4 pv = *(const float4*)(g_simA + pbase + (size_t)(i0 + pr) * JTOT + k0 + pc);
        Ps[pc + 0][pr] = pv.x; Ps[pc + 1][pr] = pv.y;
        Ps[pc + 2][pr] = pv.z; Ps[pc + 3][pr] = pv.w;
        float4 v0 = *(const float4*)(g_v + vbase + (size_t)(k0 + vr) * HD + vc);
        float4 v1 = *(const float4*)(g_v + vbase + (size_t)(k0 + vr) * HD + vc + 4);
        *(float4*)&Vs[vr][vc] = v0;
        *(float4*)&Vs[vr][vc + 4] = v1;
        __syncthreads();
#pragma unroll
        for (int kk = 0; kk < 16; kk++) {
            float a[4], bv[8];
#pragma unroll
            for (int i = 0; i < 4; i++) a[i] = Ps[kk][trow * 4 + i];
#pragma unroll
            for (int j = 0; j < 8; j++) bv[j] = Vs[kk][tcol * 8 + j];
#pragma unroll
            for (int i = 0; i < 4; i++)
#pragma unroll
                for (int j = 0; j < 8; j++) acc[i][j] = fmaf(a[i], bv[j], acc[i][j]);
        }
        __syncthreads();
    }
    const float hsg = hs_params[g];
#pragma unroll
    for (int i = 0; i < 4; i++) {
        const int si = i0 + trow * 4 + i;
#pragma unroll
        for (int j = 0; j < 8; j++) {
            const int dd = tcol * 8 + j;
            const size_t gi = ((size_t)b * SEQ + si) * DMODEL + g * HD + dd;
            const float gate = g_gate[gi];
            const float sig = 1.f / (1.f + __expf(-gate));
            g_ao[gi] = acc[i][j] * hsg * sig;
        }
    }
}

// --------------------------------------------------------------------------------
extern "C" void kernel_launch(void* const* d_in, const int* in_sizes, int n_in,
                              void* d_out, int out_size)
{
    const float* x         = (const float*)d_in[0];
    // d_in[1] = mask: all-true by construction; unused.
    const float* freqs     = (const float*)d_in[2];
    const float* Wq        = (const float*)d_in[3];
    const float* Wk        = (const float*)d_in[4];
    const float* Wv        = (const float*)d_in[5];
    const float* q_scale   = (const float*)d_in[6];
    const float* k_scale   = (const float*)d_in[7];
    const float* mem_k     = (const float*)d_in[8];
    const float* mem_v     = (const float*)d_in[9];
    const float* pre_talk  = (const float*)d_in[10];
    const float* post_talk = (const float*)d_in[11];
    const float* head_sc   = (const float*)d_in[12];
    const float* Wg        = (const float*)d_in[13];
    const float* bg        = (const float*)d_in[14];
    const float* Wo        = (const float*)d_in[15];
    float* out = (float*)d_out;

    float *p_q, *p_k, *p_v, *p_gate, *p_ao;
    cudaGetSymbolAddress((void**)&p_q, g_q);
    cudaGetSymbolAddress((void**)&p_k, g_k);
    cudaGetSymbolAddress((void**)&p_v, g_v);
    cudaGetSymbolAddress((void**)&p_gate, g_gate);
    cudaGetSymbolAddress((void**)&p_ao, g_ao);

    const dim3 gemmGrid(DMODEL / 128, (BATCH * SEQ) / 128);

    // memory K/V prefix
    mem_prefix_k<<<NH * NMEM, 128>>>(mem_k, mem_v, k_scale);

    // projections
    sgemm_k<<<gemmGrid, 256>>>(x, Wq, nullptr, p_q, 0);
    sgemm_k<<<gemmGrid, 256>>>(x, Wk, nullptr, p_k, 1);
    sgemm_k<<<gemmGrid, 256>>>(x, Wv, nullptr, p_v, 1);
    sgemm_k<<<gemmGrid, 256>>>(x, Wg, bg, p_gate, 2);

    // l2norm + rope
    const int rows = BATCH * NH * SEQ;
    norm_rope_k<<<rows, HD>>>(p_q, SEQ, 0, q_scale, freqs, 1);
    norm_rope_k<<<rows, HD>>>(p_k, JTOT, NMEM, k_scale, freqs, 1);
    norm_rope_k<<<rows, HD>>>(p_v, JTOT, NMEM, nullptr, freqs, 0);

    // sim = 10 * Q K^T   -> g_simA
    qk_gemm_k<<<dim3((JTOT + 63) / 64, SEQ / 64, BATCH * NH), 256>>>();

    // pre-talk + mask -> g_simB; softmax in place; post-talk -> g_simA
    {
        float *pA, *pB;
        cudaGetSymbolAddress((void**)&pA, g_simA);
        cudaGetSymbolAddress((void**)&pB, g_simB);
        const dim3 talkGrid((JTOT + 255) / 256, SEQ, BATCH);
        talk_k<<<talkGrid, 256>>>(pA, pB, pre_talk, 1);
        softmax_k<<<BATCH * NH * SEQ, 256>>>(pB);
        talk_k<<<talkGrid, 256>>>(pB, pA, post_talk, 0);
    }

    // out = attn @ V, * head_scale * sigmoid(gate) -> g_ao
    av_gemm_k<<<dim3(1, SEQ / 64, BATCH * NH), 256>>>(head_sc);

    // final projection -> d_out
    sgemm_k<<<gemmGrid, 256>>>(p_ao, Wo, nullptr, out, 2);
}

// round 2
// speedup vs baseline: 1.2876x; 1.2876x over previous
#include <cuda_runtime.h>
#include <math.h>
#include <float.h>

#define BATCH 2
#define SEQ 2048
#define DMODEL 2048
#define NH 16
#define HD 128
#define ROT 64
#define RHALF 32
#define NMEM 16
#define JTOT 2064
#define QKSCALE 10.0f

typedef unsigned long long ull;

// ---------------- scratch ----------------
__device__ float g_q[BATCH * NH * SEQ * HD];
__device__ float g_k[BATCH * NH * JTOT * HD];
__device__ float g_v[BATCH * NH * JTOT * HD];
__device__ float g_gate[BATCH * SEQ * DMODEL];
__device__ float g_simA[(size_t)BATCH * NH * SEQ * JTOT];
__device__ float g_simB[(size_t)BATCH * NH * SEQ * JTOT];
__device__ float g_ao[BATCH * SEQ * DMODEL];

// ---------------- f32x2 helpers ----------------
__device__ __forceinline__ void ffma2(ull& d, ull a, ull b) {
    asm("fma.rn.f32x2 %0, %1, %2, %0;" : "+l"(d) : "l"(a), "l"(b));
}
__device__ __forceinline__ ull dup2(float x) {
    ull r;
    asm("mov.b64 %0, {%1, %1};" : "=l"(r) : "r"(__float_as_uint(x)));
    return r;
}
__device__ __forceinline__ float2 unpack2(ull v) {
    float2 r;
    asm("mov.b64 {%0, %1}, %2;" : "=f"(r.x), "=f"(r.y) : "l"(v));
    return r;
}

// micro-kernel: 8x8 per thread via f32x2, from As (transposed, stride SA) and Bs
#define MICRO16(AS, BS)                                                        \
    _Pragma("unroll") for (int kk = 0; kk < 16; kk++) {                        \
        float4 a0 = *(const float4*)&AS[kk][trow * 8];                         \
        float4 a1 = *(const float4*)&AS[kk][trow * 8 + 4];                     \
        ulonglong2 b0 = *(const ulonglong2*)&BS[kk][tcol * 8];                 \
        ulonglong2 b1 = *(const ulonglong2*)&BS[kk][tcol * 8 + 4];             \
        ull bb0 = b0.x, bb1 = b0.y, bb2 = b1.x, bb3 = b1.y;                    \
        float av_[8] = {a0.x, a0.y, a0.z, a0.w, a1.x, a1.y, a1.z, a1.w};       \
        _Pragma("unroll") for (int ii = 0; ii < 8; ii++) {                     \
            ull ad = dup2(av_[ii]);                                            \
            ffma2(acc[ii][0], ad, bb0);                                        \
            ffma2(acc[ii][1], ad, bb1);                                        \
            ffma2(acc[ii][2], ad, bb2);                                        \
            ffma2(acc[ii][3], ad, bb3);                                        \
        }                                                                      \
    }

// ================= merged QKVG projection GEMM =================
// grid (64, 32): blockIdx.x>>4 selects {Wq,Wk,Wv,Wg}; 128x128 tile, BK=16, 2-stage
__global__ __launch_bounds__(256, 2) void qkvg_k(
    const float* __restrict__ x, const float* __restrict__ Wq,
    const float* __restrict__ Wk, const float* __restrict__ Wv,
    const float* __restrict__ Wg, const float* __restrict__ bg)
{
    __shared__ float As[2][16][136];
    __shared__ float Bs[2][16][128];
    const int tx = threadIdx.x;
    const int mat = blockIdx.x >> 4;
    const int colBase = (blockIdx.x & 15) * 128;
    const int rowBase = blockIdx.y * 128;
    const float* W = (mat == 0) ? Wq : (mat == 1) ? Wk : (mat == 2) ? Wv : Wg;

    const int am = tx >> 1, akq = (tx & 1) << 3;           // unused alt mapping
    (void)am; (void)akq;

    ull acc[8][4];
#pragma unroll
    for (int i = 0; i < 8; i++)
#pragma unroll
        for (int j = 0; j < 4; j++) acc[i][j] = 0ull;

    float4 aR[2], bR[2];
#pragma unroll
    for (int u = 0; u < 2; u++) {
        int idx = tx + u * 256;
        aR[u] = *(const float4*)(x + (size_t)(rowBase + (idx >> 2)) * DMODEL + ((idx & 3) << 2));
        bR[u] = *(const float4*)(W + (size_t)(idx >> 5) * DMODEL + colBase + ((idx & 31) << 2));
    }
#pragma unroll
    for (int u = 0; u < 2; u++) {
        int idx = tx + u * 256;
        int m = idx >> 2, kq = (idx & 3) << 2;
        As[0][kq + 0][m] = aR[u].x; As[0][kq + 1][m] = aR[u].y;
        As[0][kq + 2][m] = aR[u].z; As[0][kq + 3][m] = aR[u].w;
        *(float4*)&Bs[0][idx >> 5][(idx & 31) << 2] = bR[u];
    }
    __syncthreads();
    const int trow = tx >> 4, tcol = tx & 15;

    for (int t = 0; t < 128; t++) {
        const int cur = t & 1;
        if (t < 127) {
            const int k0 = (t + 1) * 16;
#pragma unroll
            for (int u = 0; u < 2; u++) {
                int idx = tx + u * 256;
                aR[u] = *(const float4*)(x + (size_t)(rowBase + (idx >> 2)) * DMODEL + k0 + ((idx & 3) << 2));
                bR[u] = *(const float4*)(W + (size_t)(k0 + (idx >> 5)) * DMODEL + colBase + ((idx & 31) << 2));
            }
        }
        MICRO16(As[cur], Bs[cur])
        if (t < 127) {
            const int nxt = cur ^ 1;
#pragma unroll
            for (int u = 0; u < 2; u++) {
                int idx = tx + u * 256;
                int m = idx >> 2, kq = (idx & 3) << 2;
                As[nxt][kq + 0][m] = aR[u].x; As[nxt][kq + 1][m] = aR[u].y;
                As[nxt][kq + 2][m] = aR[u].z; As[nxt][kq + 3][m] = aR[u].w;
                *(float4*)&Bs[nxt][idx >> 5][(idx & 31) << 2] = bR[u];
            }
        }
        __syncthreads();
    }

    const int b = rowBase >> 11;
    const int si0 = (rowBase & 2047) + trow * 8;
#pragma unroll
    for (int i = 0; i < 8; i++) {
        const int si = si0 + i;
#pragma unroll
        for (int j = 0; j < 4; j++) {
            float2 v = unpack2(acc[i][j]);
            const int c0 = colBase + tcol * 8 + j * 2;
            if (mat == 3) {
                float2 bb = *(const float2*)&bg[c0];
                float2 o = make_float2(v.x + bb.x, v.y + bb.y);
                *(float2*)&g_gate[((size_t)(b * SEQ + si)) * DMODEL + c0] = o;
            } else {
                const int h = c0 >> 7, dd = c0 & 127;
                float* dst = (mat == 0) ? g_q : (mat == 1) ? g_k : g_v;
                size_t off;
                if (mat == 0) off = (((size_t)(b * NH + h)) * SEQ + si) * HD + dd;
                else          off = (((size_t)(b * NH + h)) * JTOT + NMEM + si) * HD + dd;
                *(float2*)&dst[off] = v;
            }
        }
    }
}

// ================= output projection GEMM (plain) =================
__global__ __launch_bounds__(256, 2) void proj_k(
    const float* __restrict__ A, const float* __restrict__ W,
    float* __restrict__ C)
{
    __shared__ float As[2][16][136];
    __shared__ float Bs[2][16][128];
    const int tx = threadIdx.x;
    const int colBase = blockIdx.x * 128;
    const int rowBase = blockIdx.y * 128;

    ull acc[8][4];
#pragma unroll
    for (int i = 0; i < 8; i++)
#pragma unroll
        for (int j = 0; j < 4; j++) acc[i][j] = 0ull;

    float4 aR[2], bR[2];
#pragma unroll
    for (int u = 0; u < 2; u++) {
        int idx = tx + u * 256;
        aR[u] = *(const float4*)(A + (size_t)(rowBase + (idx >> 2)) * DMODEL + ((idx & 3) << 2));
        bR[u] = *(const float4*)(W + (size_t)(idx >> 5) * DMODEL + colBase + ((idx & 31) << 2));
    }
#pragma unroll
    for (int u = 0; u < 2; u++) {
        int idx = tx + u * 256;
        int m = idx >> 2, kq = (idx & 3) << 2;
        As[0][kq + 0][m] = aR[u].x; As[0][kq + 1][m] = aR[u].y;
        As[0][kq + 2][m] = aR[u].z; As[0][kq + 3][m] = aR[u].w;
        *(float4*)&Bs[0][idx >> 5][(idx & 31) << 2] = bR[u];
    }
    __syncthreads();
    const int trow = tx >> 4, tcol = tx & 15;

    for (int t = 0; t < 128; t++) {
        const int cur = t & 1;
        if (t < 127) {
            const int k0 = (t + 1) * 16;
#pragma unroll
            for (int u = 0; u < 2; u++) {
                int idx = tx + u * 256;
                aR[u] = *(const float4*)(A + (size_t)(rowBase + (idx >> 2)) * DMODEL + k0 + ((idx & 3) << 2));
                bR[u] = *(const float4*)(W + (size_t)(k0 + (idx >> 5)) * DMODEL + colBase + ((idx & 31) << 2));
            }
        }
        MICRO16(As[cur], Bs[cur])
        if (t < 127) {
            const int nxt = cur ^ 1;
#pragma unroll
            for (int u = 0; u < 2; u++) {
                int idx = tx + u * 256;
                int m = idx >> 2, kq = (idx & 3) << 2;
                As[nxt][kq + 0][m] = aR[u].x; As[nxt][kq + 1][m] = aR[u].y;
                As[nxt][kq + 2][m] = aR[u].z; As[nxt][kq + 3][m] = aR[u].w;
                *(float4*)&Bs[nxt][idx >> 5][(idx & 31) << 2] = bR[u];
            }
        }
        __syncthreads();
    }

#pragma unroll
    for (int i = 0; i < 8; i++) {
        const int m = rowBase + trow * 8 + i;
#pragma unroll
        for (int j = 0; j < 4; j++) {
            float2 v = unpack2(acc[i][j]);
            *(float2*)&C[(size_t)m * DMODEL + colBase + tcol * 8 + j * 2] = v;
        }
    }
}

// ================= QK^T with causal block skipping =================
// grid (17, 16, 32): (jt, it, bh). Skip jt > it+1 (fully masked).
__global__ __launch_bounds__(256, 2) void qk_k()
{
    const int jt = blockIdx.x, it = blockIdx.y, bh = blockIdx.z;
    if (jt > it + 1) return;
    __shared__ float As[2][16][136];
    __shared__ float Ks[2][16][136];
    const int tx = threadIdx.x;
    const int i0 = it * 128, j0 = jt * 128;
    const float* Aq = g_q + (size_t)bh * SEQ * HD;
    const float* Bk = g_k + (size_t)bh * JTOT * HD;

    ull acc[8][4];
#pragma unroll
    for (int i = 0; i < 8; i++)
#pragma unroll
        for (int j = 0; j < 4; j++) acc[i][j] = 0ull;

    float4 aR[2], bR[2];
#pragma unroll
    for (int u = 0; u < 2; u++) {
        int idx = tx + u * 256;
        int m = idx >> 2, kq = (idx & 3) << 2;
        aR[u] = *(const float4*)(Aq + (size_t)(i0 + m) * HD + kq);
        const int jr = j0 + m;
        bR[u] = (jr < JTOT) ? *(const float4*)(Bk + (size_t)jr * HD + kq)
                            : make_float4(0.f, 0.f, 0.f, 0.f);
    }
#pragma unroll
    for (int u = 0; u < 2; u++) {
        int idx = tx + u * 256;
        int m = idx >> 2, kq = (idx & 3) << 2;
        As[0][kq + 0][m] = aR[u].x; As[0][kq + 1][m] = aR[u].y;
        As[0][kq + 2][m] = aR[u].z; As[0][kq + 3][m] = aR[u].w;
        Ks[0][kq + 0][m] = bR[u].x; Ks[0][kq + 1][m] = bR[u].y;
        Ks[0][kq + 2][m] = bR[u].z; Ks[0][kq + 3][m] = bR[u].w;
    }
    __syncthreads();
    const int trow = tx >> 4, tcol = tx & 15;

    for (int t = 0; t < 8; t++) {
        const int cur = t & 1;
        if (t < 7) {
            const int k0 = (t + 1) * 16;
#pragma unroll
            for (int u = 0; u < 2; u++) {
                int idx = tx + u * 256;
                int m = idx >> 2, kq = (idx & 3) << 2;
                aR[u] = *(const float4*)(Aq + (size_t)(i0 + m) * HD + k0 + kq);
                const int jr = j0 + m;
                bR[u] = (jr < JTOT) ? *(const float4*)(Bk + (size_t)jr * HD + k0 + kq)
                                    : make_float4(0.f, 0.f, 0.f, 0.f);
            }
        }
        MICRO16(As[cur], Ks[cur])
        if (t < 7) {
            const int nxt = cur ^ 1;
#pragma unroll
            for (int u = 0; u < 2; u++) {
                int idx = tx + u * 256;
                int m = idx >> 2, kq = (idx & 3) << 2;
                As[nxt][kq + 0][m] = aR[u].x; As[nxt][kq + 1][m] = aR[u].y;
                As[nxt][kq + 2][m] = aR[u].z; As[nxt][kq + 3][m] = aR[u].w;
                Ks[nxt][kq + 0][m] = bR[u].x; Ks[nxt][kq + 1][m] = bR[u].y;
                Ks[nxt][kq + 2][m] = bR[u].z; Ks[nxt][kq + 3][m] = bR[u].w;
            }
        }
        __syncthreads();
    }

    float* S = g_simA + (size_t)bh * SEQ * JTOT;
#pragma unroll
    for (int i = 0; i < 8; i++) {
        const int ii = i0 + trow * 8 + i;
#pragma unroll
        for (int j = 0; j < 4; j++) {
            const int jj = j0 + tcol * 8 + j * 2;
            if (jj < JTOT) {
                float2 v = unpack2(acc[i][j]);
                v.x *= QKSCALE; v.y *= QKSCALE;
                *(float2*)&S[(size_t)ii * JTOT + jj] = v;
            }
        }
    }
}

// ================= fused pre-talk + mask + softmax + post-talk =================
// one CTA per (b,i); all 16 heads' rows in smem.
__global__ void talksm_k(const float* __restrict__ pre,
                         const float* __restrict__ post)
{
    extern __shared__ float S[];   // [16][JTOT]
    __shared__ float Tm[256], Pm[256], Red[128], Mg[16], Inv[16];
    const int t = threadIdx.x;     // 256
    const int i = blockIdx.x, b = blockIdx.y;
    Tm[t] = pre[t];
    Pm[t] = post[t];
    const int jlim = i + 17;
    const int rowLimit = min(JTOT, (i & ~127) + 144);
    const size_t base = (size_t)(b * NH) * SEQ * JTOT + (size_t)i * JTOT;
    const size_t hstr = (size_t)SEQ * JTOT;

#pragma unroll
    for (int h = 0; h < NH; h++) {
        const float* src = g_simA + base + h * hstr;
        for (int jj = t; jj < jlim; jj += 256) S[h * JTOT + jj] = src[jj];
    }
    __syncthreads();

    float mg[16];
#pragma unroll
    for (int g = 0; g < 16; g++) mg[g] = -FLT_MAX;
    for (int jj = t; jj < jlim; jj += 256) {
        float s[16];
#pragma unroll
        for (int h = 0; h < 16; h++) s[h] = S[h * JTOT + jj];
#pragma unroll
        for (int g = 0; g < 16; g++) {
            float o = 0.f;
#pragma unroll
            for (int h = 0; h < 16; h++) o = fmaf(Tm[g * 16 + h], s[h], o);
            S[g * JTOT + jj] = o;
            mg[g] = fmaxf(mg[g], o);
        }
    }
    const int lane = t & 31, warp = t >> 5;
#pragma unroll
    for (int g = 0; g < 16; g++) {
        float v = mg[g];
        for (int o = 16; o; o >>= 1) v = fmaxf(v, __shfl_xor_sync(0xffffffffu, v, o));
        if (lane == 0) Red[g * 8 + warp] = v;
    }
    __syncthreads();
    if (t < 16) {
        float v = Red[t * 8];
#pragma unroll
        for (int w = 1; w < 8; w++) v = fmaxf(v, Red[t * 8 + w]);
        Mg[t] = v;
    }
    __syncthreads();
    float M[16];
#pragma unroll
    for (int g = 0; g < 16; g++) M[g] = Mg[g];

    float sg[16];
#pragma unroll
    for (int g = 0; g < 16; g++) sg[g] = 0.f;
    for (int jj = t; jj < jlim; jj += 256) {
#pragma unroll
        for (int g = 0; g < 16; g++) {
            float e = __expf(S[g * JTOT + jj] - M[g]);
            S[g * JTOT + jj] = e;
            sg[g] += e;
        }
    }
#pragma unroll
    for (int g = 0; g < 16; g++) {
        float v = sg[g];
        for (int o = 16; o; o >>= 1) v += __shfl_xor_sync(0xffffffffu, v, o);
        if (lane == 0) Red[g * 8 + warp] = v;
    }
    __syncthreads();
    if (t < 16) {
        float v = 0.f;
#pragma unroll
        for (int w = 0; w < 8; w++) v += Red[t * 8 + w];
        Inv[t] = 1.f / v;
    }
    __syncthreads();
    float inv[16];
#pragma unroll
    for (int g = 0; g < 16; g++) inv[g] = Inv[g];

    for (int jj = t; jj < rowLimit; jj += 256) {
        if (jj < jlim) {
            float a[16];
#pragma unroll
            for (int g = 0; g < 16; g++) a[g] = S[g * JTOT + jj] * inv[g];
#pragma unroll
            for (int g2 = 0; g2 < 16; g2++) {
                float o = 0.f;
#pragma unroll
                for (int g = 0; g < 16; g++) o = fmaf(Pm[g2 * 16 + g], a[g], o);
                g_simB[base + g2 * hstr + jj] = o;
            }
        } else {
#pragma unroll
            for (int g2 = 0; g2 < 16; g2++) g_simB[base + g2 * hstr + jj] = 0.f;
        }
    }
}

// ================= attn @ V + head_scale + gating =================
// grid (16, 32): (it reversed, bh). K-loop limited to i0+144.
__global__ __launch_bounds__(256, 2) void av_k(const float* __restrict__ hs)
{
    const int it = 15 - (int)blockIdx.x;
    const int bh = blockIdx.y;
    const int b = bh >> 4, g = bh & 15;
    const int i0 = it * 128;
    const int kmax = min(JTOT, i0 + 144);
    const int NT = kmax >> 4;
    __shared__ float As[2][16][136];
    __shared__ float Bs[2][16][128];
    const int tx = threadIdx.x;
    const float* Ap = g_simB + (size_t)bh * SEQ * JTOT;
    const float* Vp = g_v + (size_t)bh * JTOT * HD;

    ull acc[8][4];
#pragma unroll
    for (int i = 0; i < 8; i++)
#pragma unroll
        for (int j = 0; j < 4; j++) acc[i][j] = 0ull;

    float4 aR[2], bR[2];
#pragma unroll
    for (int u = 0; u < 2; u++) {
        int idx = tx + u * 256;
        aR[u] = *(const float4*)(Ap + (size_t)(i0 + (idx >> 2)) * JTOT + ((idx & 3) << 2));
        bR[u] = *(const float4*)(Vp + (size_t)(idx >> 5) * HD + ((idx & 31) << 2));
    }
#pragma unroll
    for (int u = 0; u < 2; u++) {
        int idx = tx + u * 256;
        int m = idx >> 2, kq = (idx & 3) << 2;
        As[0][kq + 0][m] = aR[u].x; As[0][kq + 1][m] = aR[u].y;
        As[0][kq + 2][m] = aR[u].z; As[0][kq + 3][m] = aR[u].w;
        *(float4*)&Bs[0][idx >> 5][(idx & 31) << 2] = bR[u];
    }
    __syncthreads();
    const int trow = tx >> 4, tcol = tx & 15;

    for (int t = 0; t < NT; t++) {
        const int cur = t & 1;
        if (t < NT - 1) {
            const int k0 = (t + 1) * 16;
#pragma unroll
            for (int u = 0; u < 2; u++) {
                int idx = tx + u * 256;
                aR[u] = *(const float4*)(Ap + (size_t)(i0 + (idx >> 2)) * JTOT + k0 + ((idx & 3) << 2));
                bR[u] = *(const float4*)(Vp + (size_t)(k0 + (idx >> 5)) * HD + ((idx & 31) << 2));
            }
        }
        MICRO16(As[cur], Bs[cur])
        if (t < NT - 1) {
            const int nxt = cur ^ 1;
#pragma unroll
            for (int u = 0; u < 2; u++) {
                int idx = tx + u * 256;
                int m = idx >> 2, kq = (idx & 3) << 2;
                As[nxt][kq + 0][m] = aR[u].x; As[nxt][kq + 1][m] = aR[u].y;
                As[nxt][kq + 2][m] = aR[u].z; As[nxt][kq + 3][m] = aR[u].w;
                *(float4*)&Bs[nxt][idx >> 5][(idx & 31) << 2] = bR[u];
            }
        }
        __syncthreads();
    }

    const float hsg = hs[g];
#pragma unroll
    for (int i = 0; i < 8; i++) {
        const int si = i0 + trow * 8 + i;
#pragma unroll
        for (int j = 0; j < 4; j++) {
            float2 v = unpack2(acc[i][j]);
            const int dd = tcol * 8 + j * 2;
            const size_t gi = ((size_t)(b * SEQ + si)) * DMODEL + g * HD + dd;
            float2 gt = *(const float2*)&g_gate[gi];
            float2 o;
            o.x = v.x * hsg * (1.f / (1.f + __expf(-gt.x)));
            o.y = v.y * hsg * (1.f / (1.f + __expf(-gt.y)));
            *(float2*)&g_ao[gi] = o;
        }
    }
}

// ================= memory K/V prefix =================
__global__ void mem_prefix_k(const float* __restrict__ mem_k,
                             const float* __restrict__ mem_v,
                             const float* __restrict__ k_scale)
{
    const int idx = blockIdx.x;
    const int h = idx / NMEM, jm = idx % NMEM;
    const int t = threadIdx.x;
    float kv = mem_k[(size_t)idx * HD + t];
    float ss = kv * kv;
    __shared__ float red[4];
    for (int o = 16; o; o >>= 1) ss += __shfl_down_sync(0xffffffffu, ss, o);
    if ((t & 31) == 0) red[t >> 5] = ss;
    __syncthreads();
    const float tot = red[0] + red[1] + red[2] + red[3];
    const float inv = 1.f / fmaxf(sqrtf(tot), 1e-12f);
    const float mk = kv * inv * k_scale[t];
    const float mv = mem_v[(size_t)idx * HD + t];
    for (int b = 0; b < BATCH; b++) {
        const size_t off = (((size_t)(b * NH + h)) * JTOT + jm) * HD + t;
        g_k[off] = mk;
        g_v[off] = mv;
    }
}

// ================= l2norm*scale + RoPE =================
__global__ void norm_rope_k(float* __restrict__ buf, int rowStride, int rowOff,
                            const float* __restrict__ scale,
                            const float* __restrict__ freqs, int doNorm)
{
    const int idx = blockIdx.x;
    const int i = idx % SEQ;
    const int bh = idx / SEQ;
    float* row = buf + ((size_t)bh * rowStride + rowOff + i) * HD;
    const int t = threadIdx.x;
    float v = row[t];
    __shared__ float red[4];
    __shared__ float sh[HD];
    if (doNorm) {
        float ss = v * v;
        for (int o = 16; o; o >>= 1) ss += __shfl_down_sync(0xffffffffu, ss, o);
        if ((t & 31) == 0) red[t >> 5] = ss;
        __syncthreads();
        const float tot = red[0] + red[1] + red[2] + red[3];
        const float inv = 1.f / fmaxf(sqrtf(tot), 1e-12f);
        v = v * inv * scale[t];
    }
    sh[t] = v;
    __syncthreads();
    float outv = v;
    if (t < ROT) {
        const float f = freqs[(size_t)i * ROT + t];
        const float c = cosf(f), s = sinf(f);
        const float rot = (t < RHALF) ? -sh[t + RHALF] : sh[t - RHALF];
        outv = v * c + rot * s;
    }
    row[t] = outv;
}

// --------------------------------------------------------------------------------
extern "C" void kernel_launch(void* const* d_in, const int* in_sizes, int n_in,
                              void* d_out, int out_size)
{
    const float* x         = (const float*)d_in[0];
    const float* freqs     = (const float*)d_in[2];
    const float* Wq        = (const float*)d_in[3];
    const float* Wk        = (const float*)d_in[4];
    const float* Wv        = (const float*)d_in[5];
    const float* q_scale   = (const float*)d_in[6];
    const float* k_scale   = (const float*)d_in[7];
    const float* mem_k     = (const float*)d_in[8];
    const float* mem_v     = (const float*)d_in[9];
    const float* pre_talk  = (const float*)d_in[10];
    const float* post_talk = (const float*)d_in[11];
    const float* head_sc   = (const float*)d_in[12];
    const float* Wg        = (const float*)d_in[13];
    const float* Wo        = (const float*)d_in[15];
    float* out = (float*)d_out;

    float *p_q, *p_k, *p_v, *p_ao;
    cudaGetSymbolAddress((void**)&p_q, g_q);
    cudaGetSymbolAddress((void**)&p_k, g_k);
    cudaGetSymbolAddress((void**)&p_v, g_v);
    cudaGetSymbolAddress((void**)&p_ao, g_ao);

    const int smemTalk = NH * JTOT * sizeof(float);
    cudaFuncSetAttribute(talksm_k, cudaFuncAttributeMaxDynamicSharedMemorySize, smemTalk);

    mem_prefix_k<<<NH * NMEM, 128>>>(mem_k, mem_v, k_scale);

    qkvg_k<<<dim3(64, 32), 256>>>(x, Wq, Wk, Wv, Wg, (const float*)d_in[14]);

    const int rows = BATCH * NH * SEQ;
    norm_rope_k<<<rows, HD>>>(p_q, SEQ, 0, q_scale, freqs, 1);
    norm_rope_k<<<rows, HD>>>(p_k, JTOT, NMEM, k_scale, freqs, 1);
    norm_rope_k<<<rows, HD>>>(p_v, JTOT, NMEM, nullptr, freqs, 0);

    qk_k<<<dim3(17, 16, 32), 256>>>();

    talksm_k<<<dim3(SEQ, BATCH), 256, smemTalk>>>(pre_talk, post_talk);

    av_k<<<dim3(16, 32), 256>>>(head_sc);

    proj_k<<<dim3(16, 32), 256>>>(p_ao, Wo, out);
}

// round 4
// speedup vs baseline: 2.0078x; 1.5593x over previous
#include <cuda_runtime.h>
#include <cuda_bf16.h>
#include <math.h>
#include <float.h>
#include <stdint.h>

#define BATCH 2
#define SEQ 2048
#define DMODEL 2048
#define NH 16
#define HD 128
#define ROT 64
#define RHALF 32
#define NMEM 16
#define JTOT 2064
#define QKSCALE 10.0f

typedef unsigned long long ull;

// ---------------- scratch ----------------
__device__ float g_q[BATCH * NH * SEQ * HD];
__device__ float g_k[BATCH * NH * JTOT * HD];
__device__ float g_v[BATCH * NH * JTOT * HD];
__device__ float g_gate[BATCH * SEQ * DMODEL];
__device__ float g_simA[(size_t)BATCH * NH * SEQ * JTOT];
__device__ float g_simB[(size_t)BATCH * NH * SEQ * JTOT];
__device__ float g_ao[BATCH * SEQ * DMODEL];

#define WELEM (DMODEL * DMODEL)
__device__ __nv_bfloat16 g_xhi[BATCH * SEQ * DMODEL];
__device__ __nv_bfloat16 g_xlo[BATCH * SEQ * DMODEL];
__device__ __nv_bfloat16 g_aohi[BATCH * SEQ * DMODEL];
__device__ __nv_bfloat16 g_aolo[BATCH * SEQ * DMODEL];
__device__ __nv_bfloat16 g_wthi[5 * WELEM];   // transposed: [n][k]
__device__ __nv_bfloat16 g_wtlo[5 * WELEM];

// ---------------- PTX helpers ----------------
__device__ __forceinline__ uint32_t smem_u32(const void* p) {
    uint32_t a;
    asm("{ .reg .u64 t; cvta.to.shared.u64 t, %1; cvt.u32.u64 %0, t; }" : "=r"(a) : "l"(p));
    return a;
}
__device__ __forceinline__ void cpa16(uint32_t dst, const void* src) {
    asm volatile("cp.async.cg.shared.global [%0], [%1], 16;" :: "r"(dst), "l"(src));
}
#define CPA_COMMIT() asm volatile("cp.async.commit_group;" ::: "memory")
#define CPA_WAIT(n)  asm volatile("cp.async.wait_group %0;" :: "n"(n) : "memory")

__device__ __forceinline__ void ldm4(uint32_t& r0, uint32_t& r1, uint32_t& r2, uint32_t& r3, uint32_t a) {
    asm volatile("ldmatrix.sync.aligned.m8n8.x4.shared.b16 {%0,%1,%2,%3}, [%4];"
                 : "=r"(r0), "=r"(r1), "=r"(r2), "=r"(r3) : "r"(a));
}
__device__ __forceinline__ void mma_bf16(float* c, uint32_t a0, uint32_t a1, uint32_t a2, uint32_t a3,
                                         uint32_t b0, uint32_t b1) {
    asm volatile("mma.sync.aligned.m16n8k16.row.col.f32.bf16.bf16.f32 "
                 "{%0,%1,%2,%3}, {%4,%5,%6,%7}, {%8,%9}, {%0,%1,%2,%3};"
                 : "+f"(c[0]), "+f"(c[1]), "+f"(c[2]), "+f"(c[3])
                 : "r"(a0), "r"(a1), "r"(a2), "r"(a3), "r"(b0), "r"(b1));
}

// ---------------- f32x2 helpers (attention GEMMs) ----------------
__device__ __forceinline__ void ffma2(ull& d, ull a, ull b) {
    asm("fma.rn.f32x2 %0, %1, %2, %0;" : "+l"(d) : "l"(a), "l"(b));
}
__device__ __forceinline__ ull dup2(float x) {
    ull r;
    asm("mov.b64 %0, {%1, %1};" : "=l"(r) : "r"(__float_as_uint(x)));
    return r;
}
__device__ __forceinline__ float2 unpack2(ull v) {
    float2 r;
    asm("mov.b64 {%0, %1}, %2;" : "=f"(r.x), "=f"(r.y) : "l"(v));
    return r;
}

#define MICRO16(AS, BS)                                                        \
    _Pragma("unroll") for (int kk = 0; kk < 16; kk++) {                        \
        float4 a0 = *(const float4*)&AS[kk][trow * 8];                         \
        float4 a1 = *(const float4*)&AS[kk][trow * 8 + 4];                     \
        ulonglong2 b0 = *(const ulonglong2*)&BS[kk][tcol * 8];                 \
        ulonglong2 b1 = *(const ulonglong2*)&BS[kk][tcol * 8 + 4];             \
        ull bb0 = b0.x, bb1 = b0.y, bb2 = b1.x, bb3 = b1.y;                    \
        float av_[8] = {a0.x, a0.y, a0.z, a0.w, a1.x, a1.y, a1.z, a1.w};       \
        _Pragma("unroll") for (int ii = 0; ii < 8; ii++) {                     \
            ull ad = dup2(av_[ii]);                                            \
            ffma2(acc[ii][0], ad, bb0);                                        \
            ffma2(acc[ii][1], ad, bb1);                                        \
            ffma2(acc[ii][2], ad, bb2);                                        \
            ffma2(acc[ii][3], ad, bb3);                                        \
        }                                                                      \
    }

// ================= fp32 -> bf16 hi/lo split =================
__global__ void split_k(const float4* __restrict__ in,
                        __nv_bfloat162* __restrict__ hi,
                        __nv_bfloat162* __restrict__ lo, int n4)
{
    const int i = blockIdx.x * 256 + threadIdx.x;
    if (i >= n4) return;
    float4 v = in[i];
    __nv_bfloat16 hx = __float2bfloat16_rn(v.x), hy = __float2bfloat16_rn(v.y);
    __nv_bfloat16 hz = __float2bfloat16_rn(v.z), hw = __float2bfloat16_rn(v.w);
    hi[i * 2 + 0] = __nv_bfloat162(hx, hy);
    hi[i * 2 + 1] = __nv_bfloat162(hz, hw);
    lo[i * 2 + 0] = __nv_bfloat162(__float2bfloat16_rn(v.x - __bfloat162float(hx)),
                                   __float2bfloat16_rn(v.y - __bfloat162float(hy)));
    lo[i * 2 + 1] = __nv_bfloat162(__float2bfloat16_rn(v.z - __bfloat162float(hz)),
                                   __float2bfloat16_rn(v.w - __bfloat162float(hw)));
}

// ================= fp32 W[k][n] -> bf16 Wt[n][k] hi/lo (transpose) =================
__global__ void split_t_k(const float* __restrict__ in,
                          __nv_bfloat16* __restrict__ hi,
                          __nv_bfloat16* __restrict__ lo)
{
    __shared__ float t[32][33];
    const int x = blockIdx.x * 32 + threadIdx.x;
    const int y0 = blockIdx.y * 32 + threadIdx.y;
#pragma unroll
    for (int r = 0; r < 32; r += 8)
        t[threadIdx.y + r][threadIdx.x] = in[(size_t)(y0 + r) * DMODEL + x];
    __syncthreads();
    const int ox = blockIdx.y * 32 + threadIdx.x;
    const int oy0 = blockIdx.x * 32 + threadIdx.y;
#pragma unroll
    for (int r = 0; r < 32; r += 8) {
        float v = t[threadIdx.x][threadIdx.y + r];
        __nv_bfloat16 h = __float2bfloat16_rn(v);
        hi[(size_t)(oy0 + r) * DMODEL + ox] = h;
        lo[(size_t)(oy0 + r) * DMODEL + ox] = __float2bfloat16_rn(v - __bfloat162float(h));
    }
}

// ================= mma.sync bf16x3 dense GEMM =================
// C[4096 x 2048] = A @ W. Tile 128x128, K-chunk 32, double-buffered cp.async.
// smem stage: Ahi|Alo|Bhi|Blo planes, each 128 rows x 40 bf16 (80B stride).
#define KSTR 40
#define PLANE_B (128 * KSTR * 2)      // 10240 bytes
#define STAGE_B (4 * PLANE_B)         // 40960 bytes

__global__ __launch_bounds__(256) void gemm_mma(
    const __nv_bfloat16* __restrict__ Ahi_, const __nv_bfloat16* __restrict__ Alo_,
    int matSel, const float* __restrict__ bias, float* __restrict__ outp)
{
    extern __shared__ __nv_bfloat16 sm[];
    const int tid = threadIdx.x, wid = tid >> 5, lane = tid & 31;
    const int mat = (matSel < 0) ? (int)(blockIdx.x >> 4) : matSel;
    const int ct  = (matSel < 0) ? (int)(blockIdx.x & 15) : (int)blockIdx.x;
    const int rowBase = blockIdx.y * 128;
    const int colBase = ct * 128;
    const __nv_bfloat16* Bhi_ = g_wthi + (size_t)mat * WELEM;
    const __nv_bfloat16* Blo_ = g_wtlo + (size_t)mat * WELEM;

    const int warpM = (wid >> 2) * 64;
    const int warpN = (wid & 3) * 32;
    const uint32_t smb = smem_u32(sm);

    float acc[4][4][4];
#pragma unroll
    for (int a = 0; a < 4; a++)
#pragma unroll
        for (int b = 0; b < 4; b++)
#pragma unroll
            for (int c = 0; c < 4; c++) acc[a][b][c] = 0.f;

    auto load_chunk = [&](int c, int s) {
        const int kc = c * 32;
        const uint32_t base = smb + s * STAGE_B;
#pragma unroll
        for (int u = 0; u < 8; u++) {
            int sg = tid + u * 256;
            int plane = sg >> 9;
            int t = sg & 511;
            int row = t >> 2, part = t & 3;
            const __nv_bfloat16* src;
            if (plane == 0)      src = Ahi_ + (size_t)(rowBase + row) * DMODEL + kc + part * 8;
            else if (plane == 1) src = Alo_ + (size_t)(rowBase + row) * DMODEL + kc + part * 8;
            else if (plane == 2) src = Bhi_ + (size_t)(colBase + row) * DMODEL + kc + part * 8;
            else                 src = Blo_ + (size_t)(colBase + row) * DMODEL + kc + part * 8;
            cpa16(base + plane * PLANE_B + row * 80 + part * 16, src);
        }
        CPA_COMMIT();
    };

    // B-frag ldmatrix address: lanes grouped by 8
    const int bg_ = lane >> 3, br_ = lane & 7;
    const int b_nrow_off = ((bg_ >> 1) & 1) * 8 + br_;
    const int b_kcol_off = (bg_ & 1) * 8;
    // A-frag address
    const int a_row_off = lane & 15;
    const int a_kcol_off = (lane >> 4) * 8;

    auto compute = [&](int s) {
        const uint32_t base = smb + s * STAGE_B;
#pragma unroll
        for (int k16 = 0; k16 < 2; k16++) {
            const int kc0 = k16 * 16;
            uint32_t bh[4][2], bl[4][2];
#pragma unroll
            for (int p = 0; p < 2; p++) {
                const int nrow = warpN + p * 16 + b_nrow_off;
                const uint32_t off = nrow * 80 + (kc0 + b_kcol_off) * 2;
                ldm4(bh[p * 2][0], bh[p * 2][1], bh[p * 2 + 1][0], bh[p * 2 + 1][1],
                     base + 2 * PLANE_B + off);
                ldm4(bl[p * 2][0], bl[p * 2][1], bl[p * 2 + 1][0], bl[p * 2 + 1][1],
                     base + 3 * PLANE_B + off);
            }
            uint32_t af[4][4];
#pragma unroll
            for (int mt = 0; mt < 4; mt++) {
                const int arow = warpM + mt * 16 + a_row_off;
                ldm4(af[mt][0], af[mt][1], af[mt][2], af[mt][3],
                     base + arow * 80 + (kc0 + a_kcol_off) * 2);
            }
#pragma unroll
            for (int mt = 0; mt < 4; mt++)
#pragma unroll
                for (int nt = 0; nt < 4; nt++) {
                    mma_bf16(acc[mt][nt], af[mt][0], af[mt][1], af[mt][2], af[mt][3],
                             bh[nt][0], bh[nt][1]);
                    mma_bf16(acc[mt][nt], af[mt][0], af[mt][1], af[mt][2], af[mt][3],
                             bl[nt][0], bl[nt][1]);
                }
#pragma unroll
            for (int mt = 0; mt < 4; mt++) {
                const int arow = warpM + mt * 16 + a_row_off;
                ldm4(af[mt][0], af[mt][1], af[mt][2], af[mt][3],
                     base + PLANE_B + arow * 80 + (kc0 + a_kcol_off) * 2);
            }
#pragma unroll
            for (int mt = 0; mt < 4; mt++)
#pragma unroll
                for (int nt = 0; nt < 4; nt++)
                    mma_bf16(acc[mt][nt], af[mt][0], af[mt][1], af[mt][2], af[mt][3],
                             bh[nt][0], bh[nt][1]);
        }
    };

    load_chunk(0, 0);
    for (int c = 0; c < DMODEL / 32; c++) {
        if (c + 1 < DMODEL / 32) { load_chunk(c + 1, (c + 1) & 1); CPA_WAIT(1); }
        else CPA_WAIT(0);
        __syncthreads();
        compute(c & 1);
        __syncthreads();
    }

    auto store2 = [&](int m, int col, float v0, float v1) {
        const int b = m >> 11, si = m & 2047;
        if (mat < 3) {
            const int h = col >> 7, dd = col & 127;
            size_t off;
            if (mat == 0) off = (((size_t)(b * NH + h)) * SEQ + si) * HD + dd;
            else          off = (((size_t)(b * NH + h)) * JTOT + NMEM + si) * HD + dd;
            float* dst = (mat == 0) ? g_q : (mat == 1) ? g_k : g_v;
            *(float2*)&dst[off] = make_float2(v0, v1);
        } else if (mat == 3) {
            const size_t off = ((size_t)(b * SEQ + si)) * DMODEL + col;
            *(float2*)&g_gate[off] = make_float2(v0 + bias[col], v1 + bias[col + 1]);
        } else {
            *(float2*)&outp[(size_t)m * DMODEL + col] = make_float2(v0, v1);
        }
    };

#pragma unroll
    for (int mt = 0; mt < 4; mt++)
#pragma unroll
        for (int nt = 0; nt < 4; nt++) {
            float* c = acc[mt][nt];
            const int r0 = rowBase + warpM + mt * 16 + (lane >> 2);
            const int col = colBase + warpN + nt * 8 + (lane & 3) * 2;
            store2(r0, col, c[0], c[1]);
            store2(r0 + 8, col, c[2], c[3]);
        }
}

// ================= memory K/V prefix =================
__global__ void mem_prefix_k(const float* __restrict__ mem_k,
                             const float* __restrict__ mem_v,
                             const float* __restrict__ k_scale)
{
    const int idx = blockIdx.x;
    const int h = idx / NMEM, jm = idx % NMEM;
    const int t = threadIdx.x;
    float kv = mem_k[(size_t)idx * HD + t];
    float ss = kv * kv;
    __shared__ float red[4];
    for (int o = 16; o; o >>= 1) ss += __shfl_down_sync(0xffffffffu, ss, o);
    if ((t & 31) == 0) red[t >> 5] = ss;
    __syncthreads();
    const float tot = red[0] + red[1] + red[2] + red[3];
    const float inv = 1.f / fmaxf(sqrtf(tot), 1e-12f);
    const float mk = kv * inv * k_scale[t];
    const float mv = mem_v[(size_t)idx * HD + t];
    for (int b = 0; b < BATCH; b++) {
        const size_t off = (((size_t)(b * NH + h)) * JTOT + jm) * HD + t;
        g_k[off] = mk;
        g_v[off] = mv;
    }
}

// ================= l2norm*scale + RoPE =================
__global__ void norm_rope_k(float* __restrict__ buf, int rowStride, int rowOff,
                            const float* __restrict__ scale,
                            const float* __restrict__ freqs, int doNorm)
{
    const int idx = blockIdx.x;
    const int i = idx % SEQ;
    const int bh = idx / SEQ;
    float* row = buf + ((size_t)bh * rowStride + rowOff + i) * HD;
    const int t = threadIdx.x;
    float v = row[t];
    __shared__ float red[4];
    __shared__ float sh[HD];
    if (doNorm) {
        float ss = v * v;
        for (int o = 16; o; o >>= 1) ss += __shfl_down_sync(0xffffffffu, ss, o);
        if ((t & 31) == 0) red[t >> 5] = ss;
        __syncthreads();
        const float tot = red[0] + red[1] + red[2] + red[3];
        const float inv = 1.f / fmaxf(sqrtf(tot), 1e-12f);
        v = v * inv * scale[t];
    }
    sh[t] = v;
    __syncthreads();
    float outv = v;
    if (t < ROT) {
        const float f = freqs[(size_t)i * ROT + t];
        const float c = cosf(f), s = sinf(f);
        const float rot = (t < RHALF) ? -sh[t + RHALF] : sh[t - RHALF];
        outv = v * c + rot * s;
    }
    row[t] = outv;
}

// ================= QK^T with causal block skipping (FFMA2) =================
__global__ __launch_bounds__(256, 2) void qk_k()
{
    const int jt = blockIdx.x, it = blockIdx.y, bh = blockIdx.z;
    if (jt > it + 1) return;
    __shared__ float As[2][16][136];
    __shared__ float Ks[2][16][136];
    const int tx = threadIdx.x;
    const int i0 = it * 128, j0 = jt * 128;
    const float* Aq = g_q + (size_t)bh * SEQ * HD;
    const float* Bk = g_k + (size_t)bh * JTOT * HD;

    ull acc[8][4];
#pragma unroll
    for (int i = 0; i < 8; i++)
#pragma unroll
        for (int j = 0; j < 4; j++) acc[i][j] = 0ull;

    float4 aR[2], bR[2];
#pragma unroll
    for (int u = 0; u < 2; u++) {
        int idx = tx + u * 256;
        int m = idx >> 2, kq = (idx & 3) << 2;
        aR[u] = *(const float4*)(Aq + (size_t)(i0 + m) * HD + kq);
        const int jr = j0 + m;
        bR[u] = (jr < JTOT) ? *(const float4*)(Bk + (size_t)jr * HD + kq)
                            : make_float4(0.f, 0.f, 0.f, 0.f);
    }
#pragma unroll
    for (int u = 0; u < 2; u++) {
        int idx = tx + u * 256;
        int m = idx >> 2, kq = (idx & 3) << 2;
        As[0][kq + 0][m] = aR[u].x; As[0][kq + 1][m] = aR[u].y;
        As[0][kq + 2][m] = aR[u].z; As[0][kq + 3][m] = aR[u].w;
        Ks[0][kq + 0][m] = bR[u].x; Ks[0][kq + 1][m] = bR[u].y;
        Ks[0][kq + 2][m] = bR[u].z; Ks[0][kq + 3][m] = bR[u].w;
    }
    __syncthreads();
    const int trow = tx >> 4, tcol = tx & 15;

    for (int t = 0; t < 8; t++) {
        const int cur = t & 1;
        if (t < 7) {
            const int k0 = (t + 1) * 16;
#pragma unroll
            for (int u = 0; u < 2; u++) {
                int idx = tx + u * 256;
                int m = idx >> 2, kq = (idx & 3) << 2;
                aR[u] = *(const float4*)(Aq + (size_t)(i0 + m) * HD + k0 + kq);
                const int jr = j0 + m;
                bR[u] = (jr < JTOT) ? *(const float4*)(Bk + (size_t)jr * HD + k0 + kq)
                                    : make_float4(0.f, 0.f, 0.f, 0.f);
            }
        }
        MICRO16(As[cur], Ks[cur])
        if (t < 7) {
            const int nxt = cur ^ 1;
#pragma unroll
            for (int u = 0; u < 2; u++) {
                int idx = tx + u * 256;
                int m = idx >> 2, kq = (idx & 3) << 2;
                As[nxt][kq + 0][m] = aR[u].x; As[nxt][kq + 1][m] = aR[u].y;
                As[nxt][kq + 2][m] = aR[u].z; As[nxt][kq + 3][m] = aR[u].w;
                Ks[nxt][kq + 0][m] = bR[u].x; Ks[nxt][kq + 1][m] = bR[u].y;
                Ks[nxt][kq + 2][m] = bR[u].z; Ks[nxt][kq + 3][m] = bR[u].w;
            }
        }
        __syncthreads();
    }

    float* S = g_simA + (size_t)bh * SEQ * JTOT;
#pragma unroll
    for (int i = 0; i < 8; i++) {
        const int ii = i0 + trow * 8 + i;
#pragma unroll
        for (int j = 0; j < 4; j++) {
            const int jj = j0 + tcol * 8 + j * 2;
            if (jj < JTOT) {
                float2 v = unpack2(acc[i][j]);
                v.x *= QKSCALE; v.y *= QKSCALE;
                *(float2*)&S[(size_t)ii * JTOT + jj] = v;
            }
        }
    }
}

// ================= fused pre-talk + mask + softmax + post-talk =================
__global__ void talksm_k(const float* __restrict__ pre,
                         const float* __restrict__ post)
{
    extern __shared__ float S[];
    __shared__ float Tm[256], Pm[256], Red[128], Mg[16], Inv[16];
    const int t = threadIdx.x;
    const int i = blockIdx.x, b = blockIdx.y;
    Tm[t] = pre[t];
    Pm[t] = post[t];
    const int jlim = i + 17;
    const int rowLimit = min(JTOT, (i & ~127) + 144);
    const size_t base = (size_t)(b * NH) * SEQ * JTOT + (size_t)i * JTOT;
    const size_t hstr = (size_t)SEQ * JTOT;

#pragma unroll
    for (int h = 0; h < NH; h++) {
        const float* src = g_simA + base + h * hstr;
        for (int jj = t; jj < jlim; jj += 256) S[h * JTOT + jj] = src[jj];
    }
    __syncthreads();

    float mg[16];
#pragma unroll
    for (int g = 0; g < 16; g++) mg[g] = -FLT_MAX;
    for (int jj = t; jj < jlim; jj += 256) {
        float s[16];
#pragma unroll
        for (int h = 0; h < 16; h++) s[h] = S[h * JTOT + jj];
#pragma unroll
        for (int g = 0; g < 16; g++) {
            float o = 0.f;
#pragma unroll
            for (int h = 0; h < 16; h++) o = fmaf(Tm[g * 16 + h], s[h], o);
            S[g * JTOT + jj] = o;
            mg[g] = fmaxf(mg[g], o);
        }
    }
    const int lane = t & 31, warp = t >> 5;
#pragma unroll
    for (int g = 0; g < 16; g++) {
        float v = mg[g];
        for (int o = 16; o; o >>= 1) v = fmaxf(v, __shfl_xor_sync(0xffffffffu, v, o));
        if (lane == 0) Red[g * 8 + warp] = v;
    }
    __syncthreads();
    if (t < 16) {
        float v = Red[t * 8];
#pragma unroll
        for (int w = 1; w < 8; w++) v = fmaxf(v, Red[t * 8 + w]);
        Mg[t] = v;
    }
    __syncthreads();
    float M[16];
#pragma unroll
    for (int g = 0; g < 16; g++) M[g] = Mg[g];

    float sg[16];
#pragma unroll
    for (int g = 0; g < 16; g++) sg[g] = 0.f;
    for (int jj = t; jj < jlim; jj += 256) {
#pragma unroll
        for (int g = 0; g < 16; g++) {
            float e = __expf(S[g * JTOT + jj] - M[g]);
            S[g * JTOT + jj] = e;
            sg[g] += e;
        }
    }
#pragma unroll
    for (int g = 0; g < 16; g++) {
        float v = sg[g];
        for (int o = 16; o; o >>= 1) v += __shfl_xor_sync(0xffffffffu, v, o);
        if (lane == 0) Red[g * 8 + warp] = v;
    }
    __syncthreads();
    if (t < 16) {
        float v = 0.f;
#pragma unroll
        for (int w = 0; w < 8; w++) v += Red[t * 8 + w];
        Inv[t] = 1.f / v;
    }
    __syncthreads();
    float inv[16];
#pragma unroll
    for (int g = 0; g < 16; g++) inv[g] = Inv[g];

    for (int jj = t; jj < rowLimit; jj += 256) {
        if (jj < jlim) {
            float a[16];
#pragma unroll
            for (int g = 0; g < 16; g++) a[g] = S[g * JTOT + jj] * inv[g];
#pragma unroll
            for (int g2 = 0; g2 < 16; g2++) {
                float o = 0.f;
#pragma unroll
                for (int g = 0; g < 16; g++) o = fmaf(Pm[g2 * 16 + g], a[g], o);
                g_simB[base + g2 * hstr + jj] = o;
            }
        } else {
#pragma unroll
            for (int g2 = 0; g2 < 16; g2++) g_simB[base + g2 * hstr + jj] = 0.f;
        }
    }
}

// ================= attn @ V + head_scale + gating (FFMA2) =================
__global__ __launch_bounds__(256, 2) void av_k(const float* __restrict__ hs)
{
    const int it = 15 - (int)blockIdx.x;
    const int bh = blockIdx.y;
    const int b = bh >> 4, g = bh & 15;
    const int i0 = it * 128;
    const int kmax = min(JTOT, i0 + 144);
    const int NT = kmax >> 4;
    __shared__ float As[2][16][136];
    __shared__ float Bs[2][16][128];
    const int tx = threadIdx.x;
    const float* Ap = g_simB + (size_t)bh * SEQ * JTOT;
    const float* Vp = g_v + (size_t)bh * JTOT * HD;

    ull acc[8][4];
#pragma unroll
    for (int i = 0; i < 8; i++)
#pragma unroll
        for (int j = 0; j < 4; j++) acc[i][j] = 0ull;

    float4 aR[2], bR[2];
#pragma unroll
    for (int u = 0; u < 2; u++) {
        int idx = tx + u * 256;
        aR[u] = *(const float4*)(Ap + (size_t)(i0 + (idx >> 2)) * JTOT + ((idx & 3) << 2));
        bR[u] = *(const float4*)(Vp + (size_t)(idx >> 5) * HD + ((idx & 31) << 2));
    }
#pragma unroll
    for (int u = 0; u < 2; u++) {
        int idx = tx + u * 256;
        int m = idx >> 2, kq = (idx & 3) << 2;
        As[0][kq + 0][m] = aR[u].x; As[0][kq + 1][m] = aR[u].y;
        As[0][kq + 2][m] = aR[u].z; As[0][kq + 3][m] = aR[u].w;
        *(float4*)&Bs[0][idx >> 5][(idx & 31) << 2] = bR[u];
    }
    __syncthreads();
    const int trow = tx >> 4, tcol = tx & 15;

    for (int t = 0; t < NT; t++) {
        const int cur = t & 1;
        if (t < NT - 1) {
            const int k0 = (t + 1) * 16;
#pragma unroll
            for (int u = 0; u < 2; u++) {
                int idx = tx + u * 256;
                aR[u] = *(const float4*)(Ap + (size_t)(i0 + (idx >> 2)) * JTOT + k0 + ((idx & 3) << 2));
                bR[u] = *(const float4*)(Vp + (size_t)(k0 + (idx >> 5)) * HD + ((idx & 31) << 2));
            }
        }
        MICRO16(As[cur], Bs[cur])
        if (t < NT - 1) {
            const int nxt = cur ^ 1;
#pragma unroll
            for (int u = 0; u < 2; u++) {
                int idx = tx + u * 256;
                int m = idx >> 2, kq = (idx & 3) << 2;
                As[nxt][kq + 0][m] = aR[u].x; As[nxt][kq + 1][m] = aR[u].y;
                As[nxt][kq + 2][m] = aR[u].z; As[nxt][kq + 3][m] = aR[u].w;
                *(float4*)&Bs[nxt][idx >> 5][(idx & 31) << 2] = bR[u];
            }
        }
        __syncthreads();
    }

    const float hsg = hs[g];
#pragma unroll
    for (int i = 0; i < 8; i++) {
        const int si = i0 + trow * 8 + i;
#pragma unroll
        for (int j = 0; j < 4; j++) {
            float2 v = unpack2(acc[i][j]);
            const int dd = tcol * 8 + j * 2;
            const size_t gi = ((size_t)(b * SEQ + si)) * DMODEL + g * HD + dd;
            float2 gt = *(const float2*)&g_gate[gi];
            float2 o;
            o.x = v.x * hsg * (1.f / (1.f + __expf(-gt.x)));
            o.y = v.y * hsg * (1.f / (1.f + __expf(-gt.y)));
            *(float2*)&g_ao[gi] = o;
        }
    }
}

// --------------------------------------------------------------------------------
extern "C" void kernel_launch(void* const* d_in, const int* in_sizes, int n_in,
                              void* d_out, int out_size)
{
    const float* x         = (const float*)d_in[0];
    const float* freqs     = (const float*)d_in[2];
    const float* Wq        = (const float*)d_in[3];
    const float* Wk        = (const float*)d_in[4];
    const float* Wv        = (const float*)d_in[5];
    const float* q_scale   = (const float*)d_in[6];
    const float* k_scale   = (const float*)d_in[7];
    const float* mem_k     = (const float*)d_in[8];
    const float* mem_v     = (const float*)d_in[9];
    const float* pre_talk  = (const float*)d_in[10];
    const float* post_talk = (const float*)d_in[11];
    const float* head_sc   = (const float*)d_in[12];
    const float* Wg        = (const float*)d_in[13];
    const float* bg        = (const float*)d_in[14];
    const float* Wo        = (const float*)d_in[15];
    float* out = (float*)d_out;

    float *p_q, *p_k, *p_v, *p_ao;
    cudaGetSymbolAddress((void**)&p_q, g_q);
    cudaGetSymbolAddress((void**)&p_k, g_k);
    cudaGetSymbolAddress((void**)&p_v, g_v);
    cudaGetSymbolAddress((void**)&p_ao, g_ao);
    __nv_bfloat16 *p_xhi, *p_xlo, *p_wthi, *p_wtlo, *p_aohi, *p_aolo;
    cudaGetSymbolAddress((void**)&p_xhi, g_xhi);
    cudaGetSymbolAddress((void**)&p_xlo, g_xlo);
    cudaGetSymbolAddress((void**)&p_wthi, g_wthi);
    cudaGetSymbolAddress((void**)&p_wtlo, g_wtlo);
    cudaGetSymbolAddress((void**)&p_aohi, g_aohi);
    cudaGetSymbolAddress((void**)&p_aolo, g_aolo);

    const int smemTalk = NH * JTOT * sizeof(float);
    cudaFuncSetAttribute(talksm_k, cudaFuncAttributeMaxDynamicSharedMemorySize, smemTalk);
    cudaFuncSetAttribute(gemm_mma, cudaFuncAttributeMaxDynamicSharedMemorySize, 2 * STAGE_B);

    // ---- conversions ----
    const int xn4 = BATCH * SEQ * DMODEL / 4;
    split_k<<<(xn4 + 255) / 256, 256>>>((const float4*)x,
                                        (__nv_bfloat162*)p_xhi, (__nv_bfloat162*)p_xlo, xn4);
    const dim3 tg(64, 64), tb(32, 8);
    split_t_k<<<tg, tb>>>(Wq, p_wthi + 0 * (size_t)WELEM, p_wtlo + 0 * (size_t)WELEM);
    split_t_k<<<tg, tb>>>(Wk, p_wthi + 1 * (size_t)WELEM, p_wtlo + 1 * (size_t)WELEM);
    split_t_k<<<tg, tb>>>(Wv, p_wthi + 2 * (size_t)WELEM, p_wtlo + 2 * (size_t)WELEM);
    split_t_k<<<tg, tb>>>(Wg, p_wthi + 3 * (size_t)WELEM, p_wtlo + 3 * (size_t)WELEM);
    split_t_k<<<tg, tb>>>(Wo, p_wthi + 4 * (size_t)WELEM, p_wtlo + 4 * (size_t)WELEM);

    mem_prefix_k<<<NH * NMEM, 128>>>(mem_k, mem_v, k_scale);

    // ---- QKVG projections (mma.sync bf16x3) ----
    gemm_mma<<<dim3(64, 32), 256, 2 * STAGE_B>>>(p_xhi, p_xlo, -1, bg, nullptr);

    const int rows = BATCH * NH * SEQ;
    norm_rope_k<<<rows, HD>>>(p_q, SEQ, 0, q_scale, freqs, 1);
    norm_rope_k<<<rows, HD>>>(p_k, JTOT, NMEM, k_scale, freqs, 1);
    norm_rope_k<<<rows, HD>>>(p_v, JTOT, NMEM, nullptr, freqs, 0);

    qk_k<<<dim3(17, 16, 32), 256>>>();
    talksm_k<<<dim3(SEQ, BATCH), 256, smemTalk>>>(pre_talk, post_talk);
    av_k<<<dim3(16, 32), 256>>>(head_sc);

    // ---- output projection (mma.sync bf16x3) ----
    split_k<<<(xn4 + 255) / 256, 256>>>((const float4*)p_ao,
                                        (__nv_bfloat162*)p_aohi, (__nv_bfloat162*)p_aolo, xn4);
    gemm_mma<<<dim3(16, 32), 256, 2 * STAGE_B>>>(p_aohi, p_aolo, 4, nullptr, out);
}

// round 5
// speedup vs baseline: 2.5276x; 1.2589x over previous
#include <cuda_runtime.h>
#include <cuda_bf16.h>
#include <math.h>
#include <float.h>
#include <stdint.h>

#define BATCH 2
#define SEQ 2048
#define DMODEL 2048
#define NH 16
#define HD 128
#define ROT 64
#define RHALF 32
#define NMEM 16
#define JTOT 2064
#define KPAD 2176
#define VPAD 2080
#define JPAD 2080
#define QKSCALE 10.0f

typedef unsigned long long ull;
typedef __nv_bfloat16 bf16;

// ---------------- scratch ----------------
__device__ float g_q[BATCH * NH * SEQ * HD];
__device__ float g_k[BATCH * NH * JTOT * HD];
__device__ float g_v[BATCH * NH * JTOT * HD];
__device__ float g_gate[BATCH * SEQ * DMODEL];
__device__ float g_simA[(size_t)BATCH * NH * SEQ * JTOT];
__device__ float g_ao[BATCH * SEQ * DMODEL];

#define WELEM (DMODEL * DMODEL)
__device__ bf16 g_xhi[BATCH * SEQ * DMODEL];
__device__ bf16 g_xlo[BATCH * SEQ * DMODEL];
__device__ bf16 g_aohi[BATCH * SEQ * DMODEL];
__device__ bf16 g_aolo[BATCH * SEQ * DMODEL];
__device__ bf16 g_wthi[5 * WELEM];
__device__ bf16 g_wtlo[5 * WELEM];

__device__ bf16 g_qhi[BATCH * NH * SEQ * HD];
__device__ bf16 g_qlo[BATCH * NH * SEQ * HD];
__device__ bf16 g_khi[(size_t)BATCH * NH * KPAD * HD];
__device__ bf16 g_klo[(size_t)BATCH * NH * KPAD * HD];
__device__ bf16 g_vhi[(size_t)BATCH * NH * VPAD * HD];
__device__ bf16 g_vlo[(size_t)BATCH * NH * VPAD * HD];
__device__ bf16 g_athi[(size_t)BATCH * NH * SEQ * JPAD];
__device__ bf16 g_atlo[(size_t)BATCH * NH * SEQ * JPAD];

// ---------------- PTX helpers ----------------
__device__ __forceinline__ uint32_t smem_u32(const void* p) {
    uint32_t a;
    asm("{ .reg .u64 t; cvta.to.shared.u64 t, %1; cvt.u32.u64 %0, t; }" : "=r"(a) : "l"(p));
    return a;
}
__device__ __forceinline__ void cpa16(uint32_t dst, const void* src) {
    asm volatile("cp.async.cg.shared.global [%0], [%1], 16;" :: "r"(dst), "l"(src));
}
#define CPA_COMMIT() asm volatile("cp.async.commit_group;" ::: "memory")
#define CPA_WAIT(n)  asm volatile("cp.async.wait_group %0;" :: "n"(n) : "memory")

__device__ __forceinline__ void ldm4(uint32_t& r0, uint32_t& r1, uint32_t& r2, uint32_t& r3, uint32_t a) {
    asm volatile("ldmatrix.sync.aligned.m8n8.x4.shared.b16 {%0,%1,%2,%3}, [%4];"
                 : "=r"(r0), "=r"(r1), "=r"(r2), "=r"(r3) : "r"(a));
}
__device__ __forceinline__ void ldm4t(uint32_t& r0, uint32_t& r1, uint32_t& r2, uint32_t& r3, uint32_t a) {
    asm volatile("ldmatrix.sync.aligned.m8n8.x4.trans.shared.b16 {%0,%1,%2,%3}, [%4];"
                 : "=r"(r0), "=r"(r1), "=r"(r2), "=r"(r3) : "r"(a));
}
__device__ __forceinline__ void mma_bf16(float* c, uint32_t a0, uint32_t a1, uint32_t a2, uint32_t a3,
                                         uint32_t b0, uint32_t b1) {
    asm volatile("mma.sync.aligned.m16n8k16.row.col.f32.bf16.bf16.f32 "
                 "{%0,%1,%2,%3}, {%4,%5,%6,%7}, {%8,%9}, {%0,%1,%2,%3};"
                 : "+f"(c[0]), "+f"(c[1]), "+f"(c[2]), "+f"(c[3])
                 : "r"(a0), "r"(a1), "r"(a2), "r"(a3), "r"(b0), "r"(b1));
}

// ================= fp32 -> bf16 hi/lo split =================
__global__ void split_k(const float4* __restrict__ in,
                        __nv_bfloat162* __restrict__ hi,
                        __nv_bfloat162* __restrict__ lo, int n4)
{
    const int i = blockIdx.x * 256 + threadIdx.x;
    if (i >= n4) return;
    float4 v = in[i];
    bf16 hx = __float2bfloat16_rn(v.x), hy = __float2bfloat16_rn(v.y);
    bf16 hz = __float2bfloat16_rn(v.z), hw = __float2bfloat16_rn(v.w);
    hi[i * 2 + 0] = __nv_bfloat162(hx, hy);
    hi[i * 2 + 1] = __nv_bfloat162(hz, hw);
    lo[i * 2 + 0] = __nv_bfloat162(__float2bfloat16_rn(v.x - __bfloat162float(hx)),
                                   __float2bfloat16_rn(v.y - __bfloat162float(hy)));
    lo[i * 2 + 1] = __nv_bfloat162(__float2bfloat16_rn(v.z - __bfloat162float(hz)),
                                   __float2bfloat16_rn(v.w - __bfloat162float(hw)));
}

// ================= fp32 W[k][n] -> bf16 Wt[n][k] hi/lo =================
__global__ void split_t_k(const float* __restrict__ in,
                          bf16* __restrict__ hi, bf16* __restrict__ lo)
{
    __shared__ float t[32][33];
    const int x = blockIdx.x * 32 + threadIdx.x;
    const int y0 = blockIdx.y * 32 + threadIdx.y;
#pragma unroll
    for (int r = 0; r < 32; r += 8)
        t[threadIdx.y + r][threadIdx.x] = in[(size_t)(y0 + r) * DMODEL + x];
    __syncthreads();
    const int ox = blockIdx.y * 32 + threadIdx.x;
    const int oy0 = blockIdx.x * 32 + threadIdx.y;
#pragma unroll
    for (int r = 0; r < 32; r += 8) {
        float v = t[threadIdx.x][threadIdx.y + r];
        bf16 h = __float2bfloat16_rn(v);
        hi[(size_t)(oy0 + r) * DMODEL + ox] = h;
        lo[(size_t)(oy0 + r) * DMODEL + ox] = __float2bfloat16_rn(v - __bfloat162float(h));
    }
}

// ================= mma.sync bf16x3 dense GEMM (unchanged from R4) =================
#define KSTR 40
#define PLANE_B (128 * KSTR * 2)
#define STAGE_B (4 * PLANE_B)

__global__ __launch_bounds__(256) void gemm_mma(
    const bf16* __restrict__ Ahi_, const bf16* __restrict__ Alo_,
    int matSel, const float* __restrict__ bias, float* __restrict__ outp)
{
    extern __shared__ bf16 sm[];
    const int tid = threadIdx.x, wid = tid >> 5, lane = tid & 31;
    const int mat = (matSel < 0) ? (int)(blockIdx.x >> 4) : matSel;
    const int ct  = (matSel < 0) ? (int)(blockIdx.x & 15) : (int)blockIdx.x;
    const int rowBase = blockIdx.y * 128;
    const int colBase = ct * 128;
    const bf16* Bhi_ = g_wthi + (size_t)mat * WELEM;
    const bf16* Blo_ = g_wtlo + (size_t)mat * WELEM;

    const int warpM = (wid >> 2) * 64;
    const int warpN = (wid & 3) * 32;
    const uint32_t smb = smem_u32(sm);

    float acc[4][4][4];
#pragma unroll
    for (int a = 0; a < 4; a++)
#pragma unroll
        for (int b = 0; b < 4; b++)
#pragma unroll
            for (int c = 0; c < 4; c++) acc[a][b][c] = 0.f;

    auto load_chunk = [&](int c, int s) {
        const int kc = c * 32;
        const uint32_t base = smb + s * STAGE_B;
#pragma unroll
        for (int u = 0; u < 8; u++) {
            int sg = tid + u * 256;
            int plane = sg >> 9;
            int t = sg & 511;
            int row = t >> 2, part = t & 3;
            const bf16* src;
            if (plane == 0)      src = Ahi_ + (size_t)(rowBase + row) * DMODEL + kc + part * 8;
            else if (plane == 1) src = Alo_ + (size_t)(rowBase + row) * DMODEL + kc + part * 8;
            else if (plane == 2) src = Bhi_ + (size_t)(colBase + row) * DMODEL + kc + part * 8;
            else                 src = Blo_ + (size_t)(colBase + row) * DMODEL + kc + part * 8;
            cpa16(base + plane * PLANE_B + row * 80 + part * 16, src);
        }
        CPA_COMMIT();
    };

    const int bg_ = lane >> 3, br_ = lane & 7;
    const int b_nrow_off = ((bg_ >> 1) & 1) * 8 + br_;
    const int b_kcol_off = (bg_ & 1) * 8;
    const int a_row_off = lane & 15;
    const int a_kcol_off = (lane >> 4) * 8;

    auto compute = [&](int s) {
        const uint32_t base = smb + s * STAGE_B;
#pragma unroll
        for (int k16 = 0; k16 < 2; k16++) {
            const int kc0 = k16 * 16;
            uint32_t bh[4][2], bl[4][2];
#pragma unroll
            for (int p = 0; p < 2; p++) {
                const int nrow = warpN + p * 16 + b_nrow_off;
                const uint32_t off = nrow * 80 + (kc0 + b_kcol_off) * 2;
                ldm4(bh[p * 2][0], bh[p * 2][1], bh[p * 2 + 1][0], bh[p * 2 + 1][1],
                     base + 2 * PLANE_B + off);
                ldm4(bl[p * 2][0], bl[p * 2][1], bl[p * 2 + 1][0], bl[p * 2 + 1][1],
                     base + 3 * PLANE_B + off);
            }
            uint32_t af[4][4];
#pragma unroll
            for (int mt = 0; mt < 4; mt++) {
                const int arow = warpM + mt * 16 + a_row_off;
                ldm4(af[mt][0], af[mt][1], af[mt][2], af[mt][3],
                     base + arow * 80 + (kc0 + a_kcol_off) * 2);
            }
#pragma unroll
            for (int mt = 0; mt < 4; mt++)
#pragma unroll
                for (int nt = 0; nt < 4; nt++) {
                    mma_bf16(acc[mt][nt], af[mt][0], af[mt][1], af[mt][2], af[mt][3],
                             bh[nt][0], bh[nt][1]);
                    mma_bf16(acc[mt][nt], af[mt][0], af[mt][1], af[mt][2], af[mt][3],
                             bl[nt][0], bl[nt][1]);
                }
#pragma unroll
            for (int mt = 0; mt < 4; mt++) {
                const int arow = warpM + mt * 16 + a_row_off;
                ldm4(af[mt][0], af[mt][1], af[mt][2], af[mt][3],
                     base + PLANE_B + arow * 80 + (kc0 + a_kcol_off) * 2);
            }
#pragma unroll
            for (int mt = 0; mt < 4; mt++)
#pragma unroll
                for (int nt = 0; nt < 4; nt++)
                    mma_bf16(acc[mt][nt], af[mt][0], af[mt][1], af[mt][2], af[mt][3],
                             bh[nt][0], bh[nt][1]);
        }
    };

    load_chunk(0, 0);
    for (int c = 0; c < DMODEL / 32; c++) {
        if (c + 1 < DMODEL / 32) { load_chunk(c + 1, (c + 1) & 1); CPA_WAIT(1); }
        else CPA_WAIT(0);
        __syncthreads();
        compute(c & 1);
        __syncthreads();
    }

    auto store2 = [&](int m, int col, float v0, float v1) {
        const int b = m >> 11, si = m & 2047;
        if (mat < 3) {
            const int h = col >> 7, dd = col & 127;
            size_t off;
            if (mat == 0) off = (((size_t)(b * NH + h)) * SEQ + si) * HD + dd;
            else          off = (((size_t)(b * NH + h)) * JTOT + NMEM + si) * HD + dd;
            float* dst = (mat == 0) ? g_q : (mat == 1) ? g_k : g_v;
            *(float2*)&dst[off] = make_float2(v0, v1);
        } else if (mat == 3) {
            const size_t off = ((size_t)(b * SEQ + si)) * DMODEL + col;
            *(float2*)&g_gate[off] = make_float2(v0 + bias[col], v1 + bias[col + 1]);
        } else {
            *(float2*)&outp[(size_t)m * DMODEL + col] = make_float2(v0, v1);
        }
    };

#pragma unroll
    for (int mt = 0; mt < 4; mt++)
#pragma unroll
        for (int nt = 0; nt < 4; nt++) {
            float* c = acc[mt][nt];
            const int r0 = rowBase + warpM + mt * 16 + (lane >> 2);
            const int col = colBase + warpN + nt * 8 + (lane & 3) * 2;
            store2(r0, col, c[0], c[1]);
            store2(r0 + 8, col, c[2], c[3]);
        }
}

// ================= zero pad rows of bf16 k/v buffers =================
__global__ void zero_pad_k()
{
    const int idx = blockIdx.x * 256 + threadIdx.x;
    const int nk = BATCH * NH * (KPAD - JTOT) * HD;     // 458752
    const int nv = BATCH * NH * (VPAD - JTOT) * HD;     // 65536
    if (idx < nk) {
        const int bh = idx / ((KPAD - JTOT) * HD);
        const int r = idx % ((KPAD - JTOT) * HD);
        const size_t off = ((size_t)bh * KPAD + JTOT) * HD + r;
        g_khi[off] = __float2bfloat16(0.f);
        g_klo[off] = __float2bfloat16(0.f);
    } else if (idx < nk + nv) {
        const int j = idx - nk;
        const int bh = j / ((VPAD - JTOT) * HD);
        const int r = j % ((VPAD - JTOT) * HD);
        const size_t off = ((size_t)bh * VPAD + JTOT) * HD + r;
        g_vhi[off] = __float2bfloat16(0.f);
        g_vlo[off] = __float2bfloat16(0.f);
    }
}

// ================= memory K/V prefix -> bf16 hi/lo =================
__global__ void mem_prefix_k(const float* __restrict__ mem_k,
                             const float* __restrict__ mem_v,
                             const float* __restrict__ k_scale)
{
    const int idx = blockIdx.x;
    const int h = idx / NMEM, jm = idx % NMEM;
    const int t = threadIdx.x;
    float kv = mem_k[(size_t)idx * HD + t];
    float ss = kv * kv;
    __shared__ float red[4];
    for (int o = 16; o; o >>= 1) ss += __shfl_down_sync(0xffffffffu, ss, o);
    if ((t & 31) == 0) red[t >> 5] = ss;
    __syncthreads();
    const float tot = red[0] + red[1] + red[2] + red[3];
    const float inv = 1.f / fmaxf(sqrtf(tot), 1e-12f);
    const float mk = kv * inv * k_scale[t];
    const float mv = mem_v[(size_t)idx * HD + t];
    const bf16 kh = __float2bfloat16_rn(mk);
    const bf16 kl = __float2bfloat16_rn(mk - __bfloat162float(kh));
    const bf16 vh = __float2bfloat16_rn(mv);
    const bf16 vl = __float2bfloat16_rn(mv - __bfloat162float(vh));
    for (int b = 0; b < BATCH; b++) {
        const size_t ko = (((size_t)(b * NH + h)) * KPAD + jm) * HD + t;
        const size_t vo = (((size_t)(b * NH + h)) * VPAD + jm) * HD + t;
        g_khi[ko] = kh; g_klo[ko] = kl;
        g_vhi[vo] = vh; g_vlo[vo] = vl;
    }
}

// ================= l2norm*scale + RoPE -> bf16 hi/lo =================
__global__ void norm_rope_k(const float* __restrict__ src, int srcStride, int srcOff,
                            bf16* __restrict__ dhi, bf16* __restrict__ dlo,
                            int dstStride, int dstOff,
                            const float* __restrict__ scale,
                            const float* __restrict__ freqs, int doNorm)
{
    const int idx = blockIdx.x;
    const int i = idx % SEQ;
    const int bh = idx / SEQ;
    const float* row = src + ((size_t)bh * srcStride + srcOff + i) * HD;
    const int t = threadIdx.x;
    float v = row[t];
    __shared__ float red[4];
    __shared__ float sh[HD];
    if (doNorm) {
        float ss = v * v;
        for (int o = 16; o; o >>= 1) ss += __shfl_down_sync(0xffffffffu, ss, o);
        if ((t & 31) == 0) red[t >> 5] = ss;
        __syncthreads();
        const float tot = red[0] + red[1] + red[2] + red[3];
        const float inv = 1.f / fmaxf(sqrtf(tot), 1e-12f);
        v = v * inv * scale[t];
    }
    sh[t] = v;
    __syncthreads();
    float outv = v;
    if (t < ROT) {
        const float f = freqs[(size_t)i * ROT + t];
        const float c = cosf(f), s = sinf(f);
        const float rot = (t < RHALF) ? -sh[t + RHALF] : sh[t - RHALF];
        outv = v * c + rot * s;
    }
    const size_t off = ((size_t)bh * dstStride + dstOff + i) * HD + t;
    const bf16 h = __float2bfloat16_rn(outv);
    dhi[off] = h;
    dlo[off] = __float2bfloat16_rn(outv - __bfloat162float(h));
}

// ================= QK^T mma bf16x3, causal block skip =================
#define QK_STAGE (4 * PLANE_B)    // 40960 (reuses 128x32 plane geometry)

__global__ __launch_bounds__(256) void qk_mma()
{
    const int jt = blockIdx.x, it = blockIdx.y, bh = blockIdx.z;
    if (jt > it + 1) return;
    extern __shared__ bf16 sm[];
    const int tid = threadIdx.x, wid = tid >> 5, lane = tid & 31;
    const int i0 = it * 128, j0 = jt * 128;
    const bf16* Qhi = g_qhi + (size_t)bh * SEQ * HD;
    const bf16* Qlo = g_qlo + (size_t)bh * SEQ * HD;
    const bf16* Khi = g_khi + (size_t)bh * KPAD * HD;
    const bf16* Klo = g_klo + (size_t)bh * KPAD * HD;
    const int warpM = (wid >> 2) * 64;
    const int warpN = (wid & 3) * 32;
    const uint32_t smb = smem_u32(sm);

    float acc[4][4][4];
#pragma unroll
    for (int a = 0; a < 4; a++)
#pragma unroll
        for (int b = 0; b < 4; b++)
#pragma unroll
            for (int c = 0; c < 4; c++) acc[a][b][c] = 0.f;

    auto load_chunk = [&](int c, int s) {
        const int kc = c * 32;
        const uint32_t base = smb + s * QK_STAGE;
#pragma unroll
        for (int u = 0; u < 8; u++) {
            int sg = tid + u * 256;
            int plane = sg >> 9;
            int t = sg & 511;
            int row = t >> 2, part = t & 3;
            const bf16* src;
            if (plane == 0)      src = Qhi + (size_t)(i0 + row) * HD + kc + part * 8;
            else if (plane == 1) src = Qlo + (size_t)(i0 + row) * HD + kc + part * 8;
            else if (plane == 2) src = Khi + (size_t)(j0 + row) * HD + kc + part * 8;
            else                 src = Klo + (size_t)(j0 + row) * HD + kc + part * 8;
            cpa16(base + plane * PLANE_B + row * 80 + part * 16, src);
        }
        CPA_COMMIT();
    };

    const int bg_ = lane >> 3, br_ = lane & 7;
    const int b_nrow_off = ((bg_ >> 1) & 1) * 8 + br_;
    const int b_kcol_off = (bg_ & 1) * 8;
    const int a_row_off = lane & 15;
    const int a_kcol_off = (lane >> 4) * 8;

    auto compute = [&](int s) {
        const uint32_t base = smb + s * QK_STAGE;
#pragma unroll
        for (int k16 = 0; k16 < 2; k16++) {
            const int kc0 = k16 * 16;
            uint32_t bh_[4][2], bl_[4][2];
#pragma unroll
            for (int p = 0; p < 2; p++) {
                const int nrow = warpN + p * 16 + b_nrow_off;
                const uint32_t off = nrow * 80 + (kc0 + b_kcol_off) * 2;
                ldm4(bh_[p * 2][0], bh_[p * 2][1], bh_[p * 2 + 1][0], bh_[p * 2 + 1][1],
                     base + 2 * PLANE_B + off);
                ldm4(bl_[p * 2][0], bl_[p * 2][1], bl_[p * 2 + 1][0], bl_[p * 2 + 1][1],
                     base + 3 * PLANE_B + off);
            }
            uint32_t af[4][4];
#pragma unroll
            for (int mt = 0; mt < 4; mt++)
                ldm4(af[mt][0], af[mt][1], af[mt][2], af[mt][3],
                     base + (warpM + mt * 16 + a_row_off) * 80 + (kc0 + a_kcol_off) * 2);
#pragma unroll
            for (int mt = 0; mt < 4; mt++)
#pragma unroll
                for (int nt = 0; nt < 4; nt++) {
                    mma_bf16(acc[mt][nt], af[mt][0], af[mt][1], af[mt][2], af[mt][3],
                             bh_[nt][0], bh_[nt][1]);
                    mma_bf16(acc[mt][nt], af[mt][0], af[mt][1], af[mt][2], af[mt][3],
                             bl_[nt][0], bl_[nt][1]);
                }
#pragma unroll
            for (int mt = 0; mt < 4; mt++)
                ldm4(af[mt][0], af[mt][1], af[mt][2], af[mt][3],
                     base + PLANE_B + (warpM + mt * 16 + a_row_off) * 80 + (kc0 + a_kcol_off) * 2);
#pragma unroll
            for (int mt = 0; mt < 4; mt++)
#pragma unroll
                for (int nt = 0; nt < 4; nt++)
                    mma_bf16(acc[mt][nt], af[mt][0], af[mt][1], af[mt][2], af[mt][3],
                             bh_[nt][0], bh_[nt][1]);
        }
    };

    load_chunk(0, 0);
    for (int c = 0; c < 4; c++) {
        if (c < 3) { load_chunk(c + 1, (c + 1) & 1); CPA_WAIT(1); }
        else CPA_WAIT(0);
        __syncthreads();
        compute(c & 1);
        __syncthreads();
    }

    float* S = g_simA + (size_t)bh * SEQ * JTOT;
#pragma unroll
    for (int mt = 0; mt < 4; mt++)
#pragma unroll
        for (int nt = 0; nt < 4; nt++) {
            float* c = acc[mt][nt];
            const int r0 = i0 + warpM + mt * 16 + (lane >> 2);
            const int jj = j0 + warpN + nt * 8 + (lane & 3) * 2;
            if (jj < JTOT) {
                *(float2*)&S[(size_t)r0 * JTOT + jj] =
                    make_float2(c[0] * QKSCALE, c[1] * QKSCALE);
                *(float2*)&S[(size_t)(r0 + 8) * JTOT + jj] =
                    make_float2(c[2] * QKSCALE, c[3] * QKSCALE);
            }
        }
}

// ================= fused pre-talk + mask + softmax + post-talk -> bf16 attn ====
__global__ void talksm_k(const float* __restrict__ pre,
                         const float* __restrict__ post)
{
    extern __shared__ float S[];
    __shared__ float Tm[256], Pm[256], Red[128], Mg[16], Inv[16];
    const int t = threadIdx.x;
    const int i = blockIdx.x, b = blockIdx.y;
    Tm[t] = pre[t];
    Pm[t] = post[t];
    const int jlim = i + 17;
    const int padlim = min(JPAD, (i & ~127) + 160);
    const size_t base = (size_t)(b * NH) * SEQ * JTOT + (size_t)i * JTOT;
    const size_t abase = (size_t)(b * NH) * SEQ * JPAD + (size_t)i * JPAD;
    const size_t hstr = (size_t)SEQ * JTOT;
    const size_t ahstr = (size_t)SEQ * JPAD;

#pragma unroll
    for (int h = 0; h < NH; h++) {
        const float* src = g_simA + base + h * hstr;
        for (int jj = t; jj < jlim; jj += 256) S[h * JTOT + jj] = src[jj];
    }
    __syncthreads();

    float mg[16];
#pragma unroll
    for (int g = 0; g < 16; g++) mg[g] = -FLT_MAX;
    for (int jj = t; jj < jlim; jj += 256) {
        float s[16];
#pragma unroll
        for (int h = 0; h < 16; h++) s[h] = S[h * JTOT + jj];
#pragma unroll
        for (int g = 0; g < 16; g++) {
            float o = 0.f;
#pragma unroll
            for (int h = 0; h < 16; h++) o = fmaf(Tm[g * 16 + h], s[h], o);
            S[g * JTOT + jj] = o;
            mg[g] = fmaxf(mg[g], o);
        }
    }
    const int lane = t & 31, warp = t >> 5;
#pragma unroll
    for (int g = 0; g < 16; g++) {
        float v = mg[g];
        for (int o = 16; o; o >>= 1) v = fmaxf(v, __shfl_xor_sync(0xffffffffu, v, o));
        if (lane == 0) Red[g * 8 + warp] = v;
    }
    __syncthreads();
    if (t < 16) {
        float v = Red[t * 8];
#pragma unroll
        for (int w = 1; w < 8; w++) v = fmaxf(v, Red[t * 8 + w]);
        Mg[t] = v;
    }
    __syncthreads();
    float M[16];
#pragma unroll
    for (int g = 0; g < 16; g++) M[g] = Mg[g];

    float sg[16];
#pragma unroll
    for (int g = 0; g < 16; g++) sg[g] = 0.f;
    for (int jj = t; jj < jlim; jj += 256) {
#pragma unroll
        for (int g = 0; g < 16; g++) {
            float e = __expf(S[g * JTOT + jj] - M[g]);
            S[g * JTOT + jj] = e;
            sg[g] += e;
        }
    }
#pragma unroll
    for (int g = 0; g < 16; g++) {
        float v = sg[g];
        for (int o = 16; o; o >>= 1) v += __shfl_xor_sync(0xffffffffu, v, o);
        if (lane == 0) Red[g * 8 + warp] = v;
    }
    __syncthreads();
    if (t < 16) {
        float v = 0.f;
#pragma unroll
        for (int w = 0; w < 8; w++) v += Red[t * 8 + w];
        Inv[t] = 1.f / v;
    }
    __syncthreads();
    float inv[16];
#pragma unroll
    for (int g = 0; g < 16; g++) inv[g] = Inv[g];

    const bf16 z = __float2bfloat16(0.f);
    for (int jj = t; jj < padlim; jj += 256) {
        if (jj < jlim) {
            float a[16];
#pragma unroll
            for (int g = 0; g < 16; g++) a[g] = S[g * JTOT + jj] * inv[g];
#pragma unroll
            for (int g2 = 0; g2 < 16; g2++) {
                float o = 0.f;
#pragma unroll
                for (int g = 0; g < 16; g++) o = fmaf(Pm[g2 * 16 + g], a[g], o);
                const bf16 h = __float2bfloat16_rn(o);
                g_athi[abase + g2 * ahstr + jj] = h;
                g_atlo[abase + g2 * ahstr + jj] = __float2bfloat16_rn(o - __bfloat162float(h));
            }
        } else {
#pragma unroll
            for (int g2 = 0; g2 < 16; g2++) {
                g_athi[abase + g2 * ahstr + jj] = z;
                g_atlo[abase + g2 * ahstr + jj] = z;
            }
        }
    }
}

// ================= attn @ V mma bf16x3 + head_scale + gating =================
#define AV_VPLANE (32 * 136 * 2)              // 8704
#define AV_STAGE (2 * PLANE_B + 2 * AV_VPLANE) // 37888

__global__ __launch_bounds__(256) void av_mma(const float* __restrict__ hs)
{
    const int it = 15 - (int)blockIdx.x;
    const int bh = blockIdx.y;
    const int b = bh >> 4, g = bh & 15;
    const int i0 = it * 128;
    const int NC = 4 * it + 5;
    extern __shared__ bf16 sm[];
    const int tid = threadIdx.x, wid = tid >> 5, lane = tid & 31;
    const bf16* Ahi = g_athi + (size_t)bh * SEQ * JPAD;
    const bf16* Alo = g_atlo + (size_t)bh * SEQ * JPAD;
    const bf16* Vhi = g_vhi + (size_t)bh * VPAD * HD;
    const bf16* Vlo = g_vlo + (size_t)bh * VPAD * HD;
    const int warpM = (wid >> 2) * 64;
    const int warpN = (wid & 3) * 32;
    const uint32_t smb = smem_u32(sm);

    float acc[4][4][4];
#pragma unroll
    for (int a = 0; a < 4; a++)
#pragma unroll
        for (int b2 = 0; b2 < 4; b2++)
#pragma unroll
            for (int c = 0; c < 4; c++) acc[a][b2][c] = 0.f;

    auto load_chunk = [&](int c, int s) {
        const int kc = c * 32;
        const uint32_t base = smb + s * AV_STAGE;
#pragma unroll
        for (int u = 0; u < 8; u++) {
            int sg = tid + u * 256;
            if (sg < 1024) {
                int plane = sg >> 9, t = sg & 511;
                int row = t >> 2, part = t & 3;
                const bf16* src = (plane ? Alo : Ahi) + (size_t)(i0 + row) * JPAD + kc + part * 8;
                cpa16(base + plane * PLANE_B + row * 80 + part * 16, src);
            } else {
                int t = sg - 1024;
                int plane = t >> 9, tt = t & 511;
                int row = tt >> 4, part = tt & 15;
                const bf16* src = (plane ? Vlo : Vhi) + (size_t)(kc + row) * HD + part * 8;
                cpa16(base + 2 * PLANE_B + plane * AV_VPLANE + row * 272 + part * 16, src);
            }
        }
        CPA_COMMIT();
    };

    const int tg_ = lane >> 3, tr_ = lane & 7;
    const int v_krow_off = (tg_ & 1) * 8 + tr_;
    const int v_ncol_off = (tg_ >> 1) * 8;
    const int a_row_off = lane & 15;
    const int a_kcol_off = (lane >> 4) * 8;

    auto compute = [&](int s) {
        const uint32_t base = smb + s * AV_STAGE;
#pragma unroll
        for (int k16 = 0; k16 < 2; k16++) {
            const int kc0 = k16 * 16;
            uint32_t vh_[4][2], vl_[4][2];
#pragma unroll
            for (int p = 0; p < 2; p++) {
                const uint32_t off = (kc0 + v_krow_off) * 272 +
                                     (warpN + p * 16 + v_ncol_off) * 2;
                ldm4t(vh_[p * 2][0], vh_[p * 2][1], vh_[p * 2 + 1][0], vh_[p * 2 + 1][1],
                      base + 2 * PLANE_B + off);
                ldm4t(vl_[p * 2][0], vl_[p * 2][1], vl_[p * 2 + 1][0], vl_[p * 2 + 1][1],
                      base + 2 * PLANE_B + AV_VPLANE + off);
            }
            uint32_t af[4][4];
#pragma unroll
            for (int mt = 0; mt < 4; mt++)
                ldm4(af[mt][0], af[mt][1], af[mt][2], af[mt][3],
                     base + (warpM + mt * 16 + a_row_off) * 80 + (kc0 + a_kcol_off) * 2);
#pragma unroll
            for (int mt = 0; mt < 4; mt++)
#pragma unroll
                for (int nt = 0; nt < 4; nt++) {
                    mma_bf16(acc[mt][nt], af[mt][0], af[mt][1], af[mt][2], af[mt][3],
                             vh_[nt][0], vh_[nt][1]);
                    mma_bf16(acc[mt][nt], af[mt][0], af[mt][1], af[mt][2], af[mt][3],
                             vl_[nt][0], vl_[nt][1]);
                }
#pragma unroll
            for (int mt = 0; mt < 4; mt++)
                ldm4(af[mt][0], af[mt][1], af[mt][2], af[mt][3],
                     base + PLANE_B + (warpM + mt * 16 + a_row_off) * 80 + (kc0 + a_kcol_off) * 2);
#pragma unroll
            for (int mt = 0; mt < 4; mt++)
#pragma unroll
                for (int nt = 0; nt < 4; nt++)
                    mma_bf16(acc[mt][nt], af[mt][0], af[mt][1], af[mt][2], af[mt][3],
                             vh_[nt][0], vh_[nt][1]);
        }
    };

    load_chunk(0, 0);
    for (int c = 0; c < NC; c++) {
        if (c + 1 < NC) { load_chunk(c + 1, (c + 1) & 1); CPA_WAIT(1); }
        else CPA_WAIT(0);
        __syncthreads();
        compute(c & 1);
        __syncthreads();
    }

    const float hsg = hs[g];
#pragma unroll
    for (int mt = 0; mt < 4; mt++)
#pragma unroll
        for (int nt = 0; nt < 4; nt++) {
            float* c = acc[mt][nt];
            const int dd = warpN + nt * 8 + (lane & 3) * 2;
#pragma unroll
            for (int hrow = 0; hrow < 2; hrow++) {
                const int si = i0 + warpM + mt * 16 + (lane >> 2) + hrow * 8;
                const size_t gi = ((size_t)(b * SEQ + si)) * DMODEL + g * HD + dd;
                float2 gt = *(const float2*)&g_gate[gi];
                float2 o;
                o.x = c[hrow * 2 + 0] * hsg * (1.f / (1.f + __expf(-gt.x)));
                o.y = c[hrow * 2 + 1] * hsg * (1.f / (1.f + __expf(-gt.y)));
                *(float2*)&g_ao[gi] = o;
            }
        }
}

// --------------------------------------------------------------------------------
extern "C" void kernel_launch(void* const* d_in, const int* in_sizes, int n_in,
                              void* d_out, int out_size)
{
    const float* x         = (const float*)d_in[0];
    const float* freqs     = (const float*)d_in[2];
    const float* Wq        = (const float*)d_in[3];
    const float* Wk        = (const float*)d_in[4];
    const float* Wv        = (const float*)d_in[5];
    const float* q_scale   = (const float*)d_in[6];
    const float* k_scale   = (const float*)d_in[7];
    const float* mem_k     = (const float*)d_in[8];
    const float* mem_v     = (const float*)d_in[9];
    const float* pre_talk  = (const float*)d_in[10];
    const float* post_talk = (const float*)d_in[11];
    const float* head_sc   = (const float*)d_in[12];
    const float* Wg        = (const float*)d_in[13];
    const float* bg        = (const float*)d_in[14];
    const float* Wo        = (const float*)d_in[15];
    float* out = (float*)d_out;

    float *p_q, *p_k, *p_v, *p_ao;
    cudaGetSymbolAddress((void**)&p_q, g_q);
    cudaGetSymbolAddress((void**)&p_k, g_k);
    cudaGetSymbolAddress((void**)&p_v, g_v);
    cudaGetSymbolAddress((void**)&p_ao, g_ao);
    bf16 *p_xhi, *p_xlo, *p_wthi, *p_wtlo, *p_aohi, *p_aolo;
    bf16 *p_qhi, *p_qlo, *p_khi, *p_klo, *p_vhi, *p_vlo;
    cudaGetSymbolAddress((void**)&p_xhi, g_xhi);
    cudaGetSymbolAddress((void**)&p_xlo, g_xlo);
    cudaGetSymbolAddress((void**)&p_wthi, g_wthi);
    cudaGetSymbolAddress((void**)&p_wtlo, g_wtlo);
    cudaGetSymbolAddress((void**)&p_aohi, g_aohi);
    cudaGetSymbolAddress((void**)&p_aolo, g_aolo);
    cudaGetSymbolAddress((void**)&p_qhi, g_qhi);
    cudaGetSymbolAddress((void**)&p_qlo, g_qlo);
    cudaGetSymbolAddress((void**)&p_khi, g_khi);
    cudaGetSymbolAddress((void**)&p_klo, g_klo);
    cudaGetSymbolAddress((void**)&p_vhi, g_vhi);
    cudaGetSymbolAddress((void**)&p_vlo, g_vlo);

    const int smemTalk = NH * JTOT * sizeof(float);
    cudaFuncSetAttribute(talksm_k, cudaFuncAttributeMaxDynamicSharedMemorySize, smemTalk);
    cudaFuncSetAttribute(gemm_mma, cudaFuncAttributeMaxDynamicSharedMemorySize, 2 * STAGE_B);
    cudaFuncSetAttribute(qk_mma, cudaFuncAttributeMaxDynamicSharedMemorySize, 2 * QK_STAGE);
    cudaFuncSetAttribute(av_mma, cudaFuncAttributeMaxDynamicSharedMemorySize, 2 * AV_STAGE);

    const int xn4 = BATCH * SEQ * DMODEL / 4;
    split_k<<<(xn4 + 255) / 256, 256>>>((const float4*)x,
                                        (__nv_bfloat162*)p_xhi, (__nv_bfloat162*)p_xlo, xn4);
    const dim3 tg(64, 64), tb(32, 8);
    split_t_k<<<tg, tb>>>(Wq, p_wthi + 0 * (size_t)WELEM, p_wtlo + 0 * (size_t)WELEM);
    split_t_k<<<tg, tb>>>(Wk, p_wthi + 1 * (size_t)WELEM, p_wtlo + 1 * (size_t)WELEM);
    split_t_k<<<tg, tb>>>(Wv, p_wthi + 2 * (size_t)WELEM, p_wtlo + 2 * (size_t)WELEM);
    split_t_k<<<tg, tb>>>(Wg, p_wthi + 3 * (size_t)WELEM, p_wtlo + 3 * (size_t)WELEM);
    split_t_k<<<tg, tb>>>(Wo, p_wthi + 4 * (size_t)WELEM, p_wtlo + 4 * (size_t)WELEM);

    zero_pad_k<<<(BATCH * NH * ((KPAD - JTOT) + (VPAD - JTOT)) * HD + 255) / 256, 256>>>();
    mem_prefix_k<<<NH * NMEM, 128>>>(mem_k, mem_v, k_scale);

    gemm_mma<<<dim3(64, 32), 256, 2 * STAGE_B>>>(p_xhi, p_xlo, -1, bg, nullptr);

    const int rows = BATCH * NH * SEQ;
    norm_rope_k<<<rows, HD>>>(p_q, SEQ, 0, p_qhi, p_qlo, SEQ, 0, q_scale, freqs, 1);
    norm_rope_k<<<rows, HD>>>(p_k, JTOT, NMEM, p_khi, p_klo, KPAD, NMEM, k_scale, freqs, 1);
    norm_rope_k<<<rows, HD>>>(p_v, JTOT, NMEM, p_vhi, p_vlo, VPAD, NMEM, nullptr, freqs, 0);

    qk_mma<<<dim3(17, 16, 32), 256, 2 * QK_STAGE>>>();
    talksm_k<<<dim3(SEQ, BATCH), 256, smemTalk>>>(pre_talk, post_talk);
    av_mma<<<dim3(16, 32), 256, 2 * AV_STAGE>>>(head_sc);

    split_k<<<(xn4 + 255) / 256, 256>>>((const float4*)p_ao,
                                        (__nv_bfloat162*)p_aohi, (__nv_bfloat162*)p_aolo, xn4);
    gemm_mma<<<dim3(16, 32), 256, 2 * STAGE_B>>>(p_aohi, p_aolo, 4, nullptr, out);
}